// round 12
// baseline (speedup 1.0000x reference)
#include <cuda_runtime.h>
#include <cuda_bf16.h>
#include <cuda_fp8.h>
#include <cstddef>
#include <cstdint>

// ---------------- scratch (device globals: allocation-free) ----------------
__device__ unsigned char d_W_g [(size_t)60000 * 4096];  // per-edge [64,64] weights (e4m3, x64 scale)
__device__ uint32_t d_w2p [(size_t)32 * 4096];          // bf16x2-packed g_w2 k-pairs
__device__ float d_x_g  [(size_t)30000 * 64];
__device__ float d_x_lg [(size_t)60000 * 64];
__device__ float d_agg_g [(size_t)30000 * 64];
__device__ float d_agg_lg[(size_t)60000 * 64];
__device__ float d_cnt_g [30000];
__device__ float d_cnt_lg[60000];
__device__ float d_feat[128];

// lg piecewise-linear machinery
__device__ float d_T[64];
__device__ int   d_m;
__device__ float d_C[(size_t)65 * 4096];
__device__ float d_D[(size_t)65 * 4096];
__device__ int   d_seg[60000];
__device__ int   d_hist[65];
__device__ int   d_cur[65];
__device__ int   d_order[60000];
__device__ int   d_tile_seg[1100];
__device__ int   d_tile_base[1100];
__device__ int   d_tile_cnt[1100];
__device__ int   d_ntiles;

#define W_SCALE 64.0f
#define W_INV_SCALE 0.015625f

// ---------------- small utility kernels ----------------
__global__ void k_zero_prep() {
    int t = threadIdx.x;
    if (t < 65) d_hist[t] = 0;
    if (t == 65) d_ntiles = 0;
}

// pack w2 into bf16x2 k-pairs: d_w2p[kp][c] = (bf16(w2[2kp][c]), bf16(w2[2kp+1][c]))
__global__ void k_conv_w2(const float* __restrict__ w2) {
    int i = blockIdx.x * 256 + threadIdx.x;   // 32*4096 items
    int kp = i >> 12, c = i & 4095;
    __nv_bfloat162 p = __floats2bfloat162_rn(w2[(size_t)(2 * kp) * 4096 + c],
                                             w2[(size_t)(2 * kp + 1) * 4096 + c]);
    d_w2p[i] = *(uint32_t*)&p;
}

__global__ void k_count(const int* __restrict__ ei, int E, float* __restrict__ cnt) {
    int e = blockIdx.x * 256 + threadIdx.x;
    if (e < E) atomicAdd(&cnt[ei[E + e]], 1.0f);
}

// x0 = relu(xin @ w + b), xin [N,F], w [F,64]
__global__ void k_init_x(const float* __restrict__ xin, int F,
                         const float* __restrict__ w, const float* __restrict__ b,
                         int N, float* __restrict__ xout) {
    int idx = blockIdx.x * 256 + threadIdx.x;
    if (idx >= N * 64) return;
    int n = idx >> 6, o = idx & 63;
    const float* xr = xin + (size_t)n * F;
    float acc = b[o];
    for (int f = 0; f < F; f++) acc = fmaf(xr[f], w[f * 64 + o], acc);
    xout[idx] = fmaxf(acc, 0.f);
}

// ---------------- g-branch W build via bf16 mma.sync (m16n8k16), fp8 output ----------------
// Tile: 64 edges x 128 cols; 8 warps = 2 warp_m (32 edges, 2 m-slabs) x 4 warp_n (32 cols).
// b-fragments reused for 2 MMAs; w2 slab amortized over 64 edges; 32 accums/thread.
__global__ void k_build_W_bf16(const float* __restrict__ ea,
                               const float* __restrict__ w1, const float* __restrict__ b1,
                               const float* __restrict__ b2, int E,
                               unsigned char* __restrict__ W) {
    __shared__ uint32_t sh_hp[64][36];         // packed bf16x2 h k-pairs (64 edges x 32 pairs)
    __shared__ uint32_t sh_wp[8][132];         // packed bf16x2 w2 slab (8 k-pairs x 128 cols)
    __shared__ unsigned char sh_o[64][128];    // fp8 output stage

    int tid = threadIdx.x;
    int lane = tid & 31, wid = tid >> 5;
    int e0 = blockIdx.y * 64;
    int c0 = blockIdx.x * 128;
    int valid = min(64, E - e0);

    // stage 1: h = relu(ea @ w1 + b1); each thread computes an adjacent o-pair, packs bf16x2
#pragma unroll
    for (int k = 0; k < 8; k++) {
        int idx = k * 256 + tid;
        int el = idx >> 5, op = idx & 31;
        uint32_t packed = 0;
        if (el < valid) {
            const float* ear = ea + (size_t)(e0 + el) * 4;
            float h0 = b1[2 * op], h1 = b1[2 * op + 1];
#pragma unroll
            for (int f = 0; f < 4; f++) {
                h0 = fmaf(ear[f], w1[f * 64 + 2 * op], h0);
                h1 = fmaf(ear[f], w1[f * 64 + 2 * op + 1], h1);
            }
            __nv_bfloat162 p = __floats2bfloat162_rn(fmaxf(h0, 0.f), fmaxf(h1, 0.f));
            packed = *(uint32_t*)&p;
        }
        sh_hp[el][op] = packed;
    }

    int warp_m = wid & 1;    // 0..1 -> 32-edge group (2 m16 slabs each)
    int warp_n = wid >> 1;   // 0..3 -> 32-col slab
    int gid = lane >> 2, t4 = lane & 3;
    float c0a[4][4], c1a[4][4];
#pragma unroll
    for (int j = 0; j < 4; j++)
#pragma unroll
        for (int q = 0; q < 4; q++) { c0a[j][q] = 0.f; c1a[j][q] = 0.f; }

#pragma unroll
    for (int kc = 0; kc < 4; kc++) {           // 4 chunks of k16
        __syncthreads();
        // stage w2 slab: 8 kp x 128 cols = 1024 entries, 4 per thread
#pragma unroll
        for (int k = 0; k < 4; k++) {
            int idx = k * 256 + tid;
            int kp = idx >> 7, cc = idx & 127;
            sh_wp[kp][cc] = d_w2p[(size_t)(kc * 8 + kp) * 4096 + c0 + cc];
        }
        __syncthreads();
        int row = warp_m * 32 + gid;
        uint32_t a0 = sh_hp[row][kc * 8 + t4];
        uint32_t a1 = sh_hp[row + 8][kc * 8 + t4];
        uint32_t a2 = sh_hp[row][kc * 8 + 4 + t4];
        uint32_t a3 = sh_hp[row + 8][kc * 8 + 4 + t4];
        uint32_t a4 = sh_hp[row + 16][kc * 8 + t4];
        uint32_t a5 = sh_hp[row + 24][kc * 8 + t4];
        uint32_t a6 = sh_hp[row + 16][kc * 8 + 4 + t4];
        uint32_t a7 = sh_hp[row + 24][kc * 8 + 4 + t4];
#pragma unroll
        for (int j = 0; j < 4; j++) {
            int bn = warp_n * 32 + j * 8 + gid;
            uint32_t b0 = sh_wp[t4][bn];
            uint32_t b1r = sh_wp[t4 + 4][bn];
            asm volatile(
                "mma.sync.aligned.m16n8k16.row.col.f32.bf16.bf16.f32 "
                "{%0,%1,%2,%3}, {%4,%5,%6,%7}, {%8,%9}, {%0,%1,%2,%3};"
                : "+f"(c0a[j][0]), "+f"(c0a[j][1]), "+f"(c0a[j][2]), "+f"(c0a[j][3])
                : "r"(a0), "r"(a1), "r"(a2), "r"(a3), "r"(b0), "r"(b1r));
            asm volatile(
                "mma.sync.aligned.m16n8k16.row.col.f32.bf16.bf16.f32 "
                "{%0,%1,%2,%3}, {%4,%5,%6,%7}, {%8,%9}, {%0,%1,%2,%3};"
                : "+f"(c1a[j][0]), "+f"(c1a[j][1]), "+f"(c1a[j][2]), "+f"(c1a[j][3])
                : "r"(a4), "r"(a5), "r"(a6), "r"(a7), "r"(b0), "r"(b1r));
        }
    }

    // epilogue: + b2, scale x64, convert to fp8x2, stage in smem
    int r = lane >> 2, q = lane & 3;
#pragma unroll
    for (int j = 0; j < 4; j++) {
        int colL = warp_n * 32 + j * 8 + q * 2;
        float2 bb = *(const float2*)&b2[c0 + colL];
        int rowA = warp_m * 32 + r;
        __nv_fp8x2_storage_t pA = __nv_cvt_float2_to_fp8x2(
            make_float2((c0a[j][0] + bb.x) * W_SCALE, (c0a[j][1] + bb.y) * W_SCALE),
            __NV_SATFINITE, __NV_E4M3);
        __nv_fp8x2_storage_t pB = __nv_cvt_float2_to_fp8x2(
            make_float2((c0a[j][2] + bb.x) * W_SCALE, (c0a[j][3] + bb.y) * W_SCALE),
            __NV_SATFINITE, __NV_E4M3);
        *(unsigned short*)&sh_o[rowA][colL]     = (unsigned short)pA;
        *(unsigned short*)&sh_o[rowA + 8][colL] = (unsigned short)pB;
        __nv_fp8x2_storage_t pC = __nv_cvt_float2_to_fp8x2(
            make_float2((c1a[j][0] + bb.x) * W_SCALE, (c1a[j][1] + bb.y) * W_SCALE),
            __NV_SATFINITE, __NV_E4M3);
        __nv_fp8x2_storage_t pD = __nv_cvt_float2_to_fp8x2(
            make_float2((c1a[j][2] + bb.x) * W_SCALE, (c1a[j][3] + bb.y) * W_SCALE),
            __NV_SATFINITE, __NV_E4M3);
        *(unsigned short*)&sh_o[rowA + 16][colL] = (unsigned short)pC;
        *(unsigned short*)&sh_o[rowA + 24][colL] = (unsigned short)pD;
    }
    __syncthreads();

    // coalesced copy out: 64 rows x 128B, 16B vectors (512 uint4, 2 per thread)
    const uint4* src = (const uint4*)&sh_o[0][0];
#pragma unroll
    for (int k = 0; k < 2; k++) {
        int idx = k * 256 + tid;
        int row = idx >> 3, chunk = idx & 7;
        if (row < valid)
            *(uint4*)&W[(size_t)(e0 + row) * 4096 + c0 + chunk * 16] = src[idx];
    }
}

// ---------------- fused msg: g blocks stream fp8 W (full-line loads); lg blocks smem tiles ----------------
__global__ void k_msg_both(const float* __restrict__ xg, const unsigned char* __restrict__ Wg,
                           const int* __restrict__ eig, int Eg, float* __restrict__ aggg, int nbg,
                           const float* __restrict__ xlg, const float* __restrict__ ealg,
                           const int* __restrict__ eilg, int Elg, float* __restrict__ agglg) {
    __shared__ float sC[4096], sD[4096];
    int tid = threadIdx.x;  // 256
    int wid = tid >> 5, lane = tid & 31;

    if ((int)blockIdx.x < nbg) {
        int e = (blockIdx.x * 256 + tid) >> 5;
        if (e >= Eg) return;
        int src = eig[e], tgt = eig[Eg + e];
        int half = lane >> 4, q = lane & 15;
        const unsigned char* Wr = Wg + (size_t)e * 4096;
        const float* xs = xg + (size_t)src * 64;
        float x0 = xs[lane], x1 = xs[lane + 32];
        float a0 = 0.f, a1 = 0.f, a2 = 0.f, a3 = 0.f;
#pragma unroll 8
        for (int jj = 0; jj < 32; jj++) {
            int i = 2 * jj + half;
            float xv = __shfl_sync(0xffffffffu, (jj < 16) ? x0 : x1, 2 * (jj & 15) + half);
            uint32_t w4 = *(const uint32_t*)(Wr + i * 64 + q * 4);
            __half2 lo = __half2(__nv_cvt_fp8x2_to_halfraw2(
                (__nv_fp8x2_storage_t)(w4 & 0xFFFFu), __NV_E4M3));
            __half2 hi = __half2(__nv_cvt_fp8x2_to_halfraw2(
                (__nv_fp8x2_storage_t)(w4 >> 16), __NV_E4M3));
            float2 f0 = __half22float2(lo), f1 = __half22float2(hi);
            a0 = fmaf(xv, f0.x, a0);
            a1 = fmaf(xv, f0.y, a1);
            a2 = fmaf(xv, f1.x, a2);
            a3 = fmaf(xv, f1.y, a3);
        }
        a0 += __shfl_xor_sync(0xffffffffu, a0, 16);
        a1 += __shfl_xor_sync(0xffffffffu, a1, 16);
        a2 += __shfl_xor_sync(0xffffffffu, a2, 16);
        a3 += __shfl_xor_sync(0xffffffffu, a3, 16);
        if (half == 0) {
            float* ag = aggg + (size_t)tgt * 64 + q * 4;
            atomicAdd(ag,     a0 * W_INV_SCALE);
            atomicAdd(ag + 1, a1 * W_INV_SCALE);
            atomicAdd(ag + 2, a2 * W_INV_SCALE);
            atomicAdd(ag + 3, a3 * W_INV_SCALE);
        }
    } else {
        int bt = blockIdx.x - nbg;
        if (bt >= d_ntiles) return;
        int s = d_tile_seg[bt], base = d_tile_base[bt], cnt = d_tile_cnt[bt];
        const float* C = d_C + (size_t)s * 4096;
        const float* Dp = d_D + (size_t)s * 4096;
        for (int i = tid; i < 4096; i += 256) { sC[i] = C[i]; sD[i] = Dp[i]; }
        __syncthreads();
        const float2* C2 = (const float2*)sC;
        const float2* D2 = (const float2*)sD;
#pragma unroll
        for (int p = 0; p < 4; p++) {
            int slotA = p * 16 + wid * 2;
            int slotB = slotA + 1;
            bool vA = slotA < cnt, vB = slotB < cnt;
            int eA = vA ? d_order[base + slotA] : 0;
            int eB = vB ? d_order[base + slotB] : 0;
            int srcA = eilg[eA], tgtA = eilg[Elg + eA];
            int srcB = eilg[eB], tgtB = eilg[Elg + eB];
            float eaA = ealg[eA], eaB = ealg[eB];
            float xA0 = vA ? xlg[(size_t)srcA * 64 + lane] : 0.f;
            float xA1 = vA ? xlg[(size_t)srcA * 64 + lane + 32] : 0.f;
            float xB0 = vB ? xlg[(size_t)srcB * 64 + lane] : 0.f;
            float xB1 = vB ? xlg[(size_t)srcB * 64 + lane + 32] : 0.f;
            float cA0 = 0, cA1 = 0, dA0 = 0, dA1 = 0;
            float cB0 = 0, cB1 = 0, dB0 = 0, dB1 = 0;
#pragma unroll 8
            for (int i = 0; i < 64; i++) {
                float2 cv = C2[i * 32 + lane];
                float2 dv = D2[i * 32 + lane];
                float xa = __shfl_sync(0xffffffffu, (i < 32) ? xA0 : xA1, i & 31);
                float xb = __shfl_sync(0xffffffffu, (i < 32) ? xB0 : xB1, i & 31);
                cA0 = fmaf(xa, cv.x, cA0); cA1 = fmaf(xa, cv.y, cA1);
                dA0 = fmaf(xa, dv.x, dA0); dA1 = fmaf(xa, dv.y, dA1);
                cB0 = fmaf(xb, cv.x, cB0); cB1 = fmaf(xb, cv.y, cB1);
                dB0 = fmaf(xb, dv.x, dB0); dB1 = fmaf(xb, dv.y, dB1);
            }
            if (vA) {
                float* ag = agglg + (size_t)tgtA * 64 + lane * 2;
                atomicAdd(ag,     fmaf(eaA, dA0, cA0));
                atomicAdd(ag + 1, fmaf(eaA, dA1, cA1));
            }
            if (vB) {
                float* ag = agglg + (size_t)tgtB * 64 + lane * 2;
                atomicAdd(ag,     fmaf(eaB, dB0, cB0));
                atomicAdd(ag + 1, fmaf(eaB, dB1, cB1));
            }
        }
    }
}

// ---------------- fused node update ----------------
__global__ void k_update_both(float* __restrict__ xg, const float* __restrict__ rootg,
                              const float* __restrict__ biasg, const float* __restrict__ cntg,
                              float* __restrict__ aggg, int Ng, int nbg,
                              float* __restrict__ xlg, const float* __restrict__ rootlg,
                              const float* __restrict__ biaslg, const float* __restrict__ cntlg,
                              float* __restrict__ agglg, int Nlg) {
    __shared__ float sroot[4096];
    __shared__ float sx[8][64];
    int t = threadIdx.x;  // 512
    int b = blockIdx.x;
    float* x; const float *root, *bias, *cnt; float* agg; int N;
    if (b < nbg) { x = xg; root = rootg; bias = biasg; cnt = cntg; agg = aggg; N = Ng; }
    else { b -= nbg; x = xlg; root = rootlg; bias = biaslg; cnt = cntlg; agg = agglg; N = Nlg; }

    for (int k = t; k < 4096; k += 512) sroot[k] = root[k];
    int nl = t >> 6, o = t & 63;
    int n = b * 8 + nl;
    if (n < N) sx[nl][o] = x[(size_t)n * 64 + o];
    __syncthreads();
    if (n >= N) return;
    float acc = bias[o] + agg[(size_t)n * 64 + o] / fmaxf(cnt[n], 1.0f);
#pragma unroll
    for (int i = 0; i < 64; i++) acc = fmaf(sx[nl][i], sroot[i * 64 + o], acc);
    x[(size_t)n * 64 + o] = fmaxf(acc, 0.f);
    agg[(size_t)n * 64 + o] = 0.f;
}

// ---------------- lg piecewise-linear precompute ----------------
__global__ void k_lg_prep(const float* __restrict__ w1, const float* __restrict__ b1) {
    __shared__ float ts[64];
    __shared__ int cnt;
    int j = threadIdx.x;  // 64
    if (j == 0) cnt = 0;
    __syncthreads();
    float w = w1[j], b = b1[j];
    if (w != 0.f) {
        float t = -b / w;
        if (t > 0.f && t < 1.f) {
            int p = atomicAdd(&cnt, 1);
            ts[p] = t;
        }
    }
    __syncthreads();
    if (j == 0) {
        for (int i = 1; i < cnt; i++) {
            float v = ts[i];
            int k = i;
            while (k > 0 && ts[k - 1] > v) { ts[k] = ts[k - 1]; k--; }
            ts[k] = v;
        }
        d_m = cnt;
        for (int i = 0; i < cnt; i++) d_T[i] = ts[i];
    }
}

__global__ void k_lg_tables(const float* __restrict__ w1, const float* __restrict__ b1,
                            const float* __restrict__ w2, const float* __restrict__ b2) {
    int s = blockIdx.x;
    int m = d_m;
    if (s > m) return;
    float lo = (s == 0) ? 0.f : d_T[s - 1];
    float hi = (s == m) ? 1.f : d_T[s];
    float mid = 0.5f * (lo + hi);
    __shared__ float cb[64], cw[64];
    int t = threadIdx.x;  // 256
    if (t < 64) {
        float w = w1[t], b = b1[t];
        bool act = (fmaf(w, mid, b) > 0.f);
        cb[t] = act ? b : 0.f;
        cw[t] = act ? w : 0.f;
    }
    __syncthreads();
    for (int io = t; io < 4096; io += 256) {
        float c = b2[io], d = 0.f;
#pragma unroll 8
        for (int j = 0; j < 64; j++) {
            float wv = w2[(size_t)j * 4096 + io];
            c = fmaf(cb[j], wv, c);
            d = fmaf(cw[j], wv, d);
        }
        d_C[(size_t)s * 4096 + io] = c;
        d_D[(size_t)s * 4096 + io] = d;
    }
}

__global__ void k_lg_seg(const float* __restrict__ ea, int E) {
    int e = blockIdx.x * 256 + threadIdx.x;
    if (e >= E) return;
    float v = ea[e];
    int lo = 0, hi = d_m;
    while (lo < hi) {
        int mid = (lo + hi) >> 1;
        if (d_T[mid] <= v) lo = mid + 1; else hi = mid;
    }
    d_seg[e] = lo;
    atomicAdd(&d_hist[lo], 1);
}

__global__ void k_lg_scan() {
    __shared__ int soff[66], stbase[66], shist[65];
    int ns = d_m + 1;
    int t = threadIdx.x;  // 128
    if (t < ns) shist[t] = d_hist[t];
    __syncthreads();
    if (t == 0) {
        int off = 0, tb = 0;
        for (int s = 0; s < ns; s++) {
            soff[s] = off;
            stbase[s] = tb;
            off += shist[s];
            tb += (shist[s] + 63) >> 6;
        }
        d_ntiles = tb;
    }
    __syncthreads();
    for (int s = t; s < ns; s += blockDim.x) {
        d_cur[s] = soff[s];
        int h = shist[s];
        int nt = (h + 63) >> 6;
        for (int k = 0; k < nt; k++) {
            int idx = stbase[s] + k;
            d_tile_seg[idx] = s;
            d_tile_base[idx] = soff[s] + k * 64;
            d_tile_cnt[idx] = min(64, h - k * 64);
        }
    }
}

__global__ void k_lg_scatter(int E) {
    int e = blockIdx.x * 256 + threadIdx.x;
    if (e >= E) return;
    int s = d_seg[e];
    int p = atomicAdd(&d_cur[s], 1);
    d_order[p] = e;
}

// ---------------- fused sum pooling ----------------
__global__ void k_pool_both(const float* __restrict__ xg, int Ng,
                            const float* __restrict__ xlg, int Nlg,
                            float* __restrict__ out) {
    __shared__ float sh[256];
    int t = threadIdx.x;
    int o = t & 63, g = t >> 6;
    const float* x; int N; float* op;
    int b = blockIdx.x;
    if (b < 120) { x = xg; N = Ng; op = out; }
    else { b -= 120; x = xlg; N = Nlg; op = out + 64; }
    float acc = 0.f;
#pragma unroll 4
    for (int n = b * 4 + g; n < N; n += 120 * 4)
        acc += x[(size_t)n * 64 + o];
    sh[t] = acc;
    __syncthreads();
    if (g == 0)
        atomicAdd(&op[o], sh[o] + sh[64 + o] + sh[128 + o] + sh[192 + o]);
}

// ---------------- head MLP ----------------
__global__ void k_head(const float* __restrict__ adduct,
                       const float* __restrict__ bw, const float* __restrict__ bb,
                       const float* __restrict__ l1w, const float* __restrict__ l1b,
                       const float* __restrict__ l2w, const float* __restrict__ l2b,
                       float* __restrict__ out) {
    __shared__ float a[384];
    __shared__ float red[384];
    int t = threadIdx.x;  // 384
    float acc = bb[t];
#pragma unroll 8
    for (int i = 0; i < 128; i++) acc = fmaf(d_feat[i], bw[i * 384 + t], acc);
    for (int k = 0; k < 3; k++) acc = fmaf(adduct[k], bw[(128 + k) * 384 + t], acc);
    a[t] = fmaxf(acc, 0.f);
    __syncthreads();
    for (int l = 0; l < 6; l++) {
        float s = l1b[t];
#pragma unroll 8
        for (int i = 0; i < 384; i++) s = fmaf(a[i], l1w[i * 384 + t], s);
        __syncthreads();
        a[t] = fmaxf(s, 0.f);
        __syncthreads();
    }
    red[t] = a[t] * l2w[t];
    __syncthreads();
    for (int s = 192; s >= 6; s >>= 1) {
        if (t < s) red[t] += red[t + s];
        __syncthreads();
    }
    if (t == 0)
        out[0] = red[0] + red[1] + red[2] + red[3] + red[4] + red[5] + l2b[0];
}

// ---------------- launch ----------------
extern "C" void kernel_launch(void* const* d_in, const int* in_sizes, int n_in,
                              void* d_out, int out_size) {
    const float* gx       = (const float*)d_in[0];
    const int*   g_ei     = (const int*)  d_in[1];
    const float* g_ea     = (const float*)d_in[2];
    const float* lgx      = (const float*)d_in[3];
    const int*   lg_ei    = (const int*)  d_in[4];
    const float* lg_ea    = (const float*)d_in[5];
    const float* adduct   = (const float*)d_in[6];
    const float* lin0_w   = (const float*)d_in[7];
    const float* lin0_b   = (const float*)d_in[8];
    const float* g_w1     = (const float*)d_in[9];
    const float* g_b1     = (const float*)d_in[10];
    const float* g_w2     = (const float*)d_in[11];
    const float* g_b2     = (const float*)d_in[12];
    const float* g_root   = (const float*)d_in[13];
    const float* g_bias   = (const float*)d_in[14];
    const float* lin0lg_w = (const float*)d_in[15];
    const float* lin0lg_b = (const float*)d_in[16];
    const float* lg_w1    = (const float*)d_in[17];
    const float* lg_b1    = (const float*)d_in[18];
    const float* lg_w2    = (const float*)d_in[19];
    const float* lg_b2    = (const float*)d_in[20];
    const float* lg_root  = (const float*)d_in[21];
    const float* lg_bias  = (const float*)d_in[22];
    const float* bott_w   = (const float*)d_in[23];
    const float* bott_b   = (const float*)d_in[24];
    const float* lin1_w   = (const float*)d_in[25];
    const float* lin1_b   = (const float*)d_in[26];
    const float* lin2_w   = (const float*)d_in[27];
    const float* lin2_b   = (const float*)d_in[28];

    const int N_G = 30000, E_G = 60000, N_LG = 60000, E_LG = 60000;

    unsigned char* W_g;
    float *x_g, *x_lg, *agg_g, *agg_lg, *cnt_g, *cnt_lg, *feat;
    cudaGetSymbolAddress((void**)&W_g,    d_W_g);
    cudaGetSymbolAddress((void**)&x_g,    d_x_g);
    cudaGetSymbolAddress((void**)&x_lg,   d_x_lg);
    cudaGetSymbolAddress((void**)&agg_g,  d_agg_g);
    cudaGetSymbolAddress((void**)&agg_lg, d_agg_lg);
    cudaGetSymbolAddress((void**)&cnt_g,  d_cnt_g);
    cudaGetSymbolAddress((void**)&cnt_lg, d_cnt_lg);
    cudaGetSymbolAddress((void**)&feat,   d_feat);

    // side stream + fork/join events
    cudaStream_t s2;
    cudaStreamCreateWithFlags(&s2, cudaStreamNonBlocking);
    cudaEvent_t evFork, evJoin;
    cudaEventCreateWithFlags(&evFork, cudaEventDisableTiming);
    cudaEventCreateWithFlags(&evJoin, cudaEventDisableTiming);

    // zero scratch (async memsets; not kernel launches)
    cudaMemsetAsync(agg_g,  0, (size_t)N_G  * 64 * sizeof(float));
    cudaMemsetAsync(agg_lg, 0, (size_t)N_LG * 64 * sizeof(float));
    cudaMemsetAsync(cnt_g,  0, N_G  * sizeof(float));
    cudaMemsetAsync(cnt_lg, 0, N_LG * sizeof(float));
    cudaMemsetAsync(feat,   0, 128 * sizeof(float));
    cudaEventRecord(evFork, 0);

    // main stream: conv(1), count(2), count(3), BUILD(4) -> ncu target
    k_conv_w2<<<(32 * 4096) / 256, 256>>>(g_w2);
    k_count<<<(E_G + 255) / 256, 256>>>(g_ei, E_G, cnt_g);
    k_count<<<(E_LG + 255) / 256, 256>>>(lg_ei, E_LG, cnt_lg);
    dim3 gw(4096 / 128, (E_G + 63) / 64);
    k_build_W_bf16<<<gw, 256>>>(g_ea, g_w1, g_b1, g_b2, E_G, W_g);

    // side stream: inits + lg prep, overlapped with build
    cudaStreamWaitEvent(s2, evFork, 0);
    k_init_x<<<(N_G * 64 + 255) / 256, 256, 0, s2>>>(gx, 20, lin0_w, lin0_b, N_G, x_g);
    k_init_x<<<(N_LG * 64 + 255) / 256, 256, 0, s2>>>(lgx, 5, lin0lg_w, lin0lg_b, N_LG, x_lg);
    k_zero_prep<<<1, 128, 0, s2>>>();
    k_lg_prep<<<1, 64, 0, s2>>>(lg_w1, lg_b1);
    k_lg_tables<<<65, 256, 0, s2>>>(lg_w1, lg_b1, lg_w2, lg_b2);
    k_lg_seg<<<(E_LG + 255) / 256, 256, 0, s2>>>(lg_ea, E_LG);
    k_lg_scan<<<1, 128, 0, s2>>>();
    k_lg_scatter<<<(E_LG + 255) / 256, 256, 0, s2>>>(E_LG);
    cudaEventRecord(evJoin, s2);
    cudaStreamWaitEvent(0, evJoin, 0);

    // 3 NNConv iterations, g+lg fused per phase
    const int nbg_msg = E_G / 8;
    const int lg_tiles_max = ((E_LG / 64 + 66) + 31) & ~31;
    const int nbg_upd = (N_G + 7) / 8;
    const int nblg_upd = (N_LG + 7) / 8;
    for (int it = 0; it < 3; it++) {
        k_msg_both<<<nbg_msg + lg_tiles_max, 256>>>(
            x_g, W_g, g_ei, E_G, agg_g, nbg_msg,
            x_lg, lg_ea, lg_ei, E_LG, agg_lg);
        k_update_both<<<nbg_upd + nblg_upd, 512>>>(
            x_g, g_root, g_bias, cnt_g, agg_g, N_G, nbg_upd,
            x_lg, lg_root, lg_bias, cnt_lg, agg_lg, N_LG);
    }

    // fused sum pooling
    k_pool_both<<<240, 256>>>(x_g, N_G, x_lg, N_LG, feat);

    // head MLP -> scalar
    k_head<<<1, 384>>>(adduct, bott_w, bott_b, lin1_w, lin1_b, lin2_w, lin2_b,
                       (float*)d_out);
}

// round 13
// speedup vs baseline: 1.0983x; 1.0983x over previous
#include <cuda_runtime.h>
#include <cuda_bf16.h>
#include <cuda_fp8.h>
#include <cstddef>
#include <cstdint>

// ---------------- scratch (device globals: allocation-free) ----------------
__device__ unsigned char d_W_g [(size_t)60000 * 4096];  // per-edge [64,64] weights (e4m3, x64 scale)
__device__ uint32_t d_w2p [(size_t)32 * 4096];          // bf16x2-packed g_w2 k-pairs
__device__ uint32_t d_hp  [(size_t)60000 * 32];         // bf16x2-packed h k-pairs per edge
__device__ float d_x_g  [(size_t)30000 * 64];
__device__ float d_x_lg [(size_t)60000 * 64];
__device__ float d_agg_g [(size_t)30000 * 64];
__device__ float d_agg_lg[(size_t)60000 * 64];
__device__ float d_cnt_g [30000];
__device__ float d_cnt_lg[60000];
__device__ float d_feat[128];

// lg piecewise-linear machinery
__device__ float d_T[64];
__device__ int   d_m;
__device__ float d_C[(size_t)65 * 4096];
__device__ float d_D[(size_t)65 * 4096];
__device__ int   d_seg[60000];
__device__ int   d_hist[65];
__device__ int   d_cur[65];
__device__ int   d_order[60000];
__device__ int   d_tile_seg[1100];
__device__ int   d_tile_base[1100];
__device__ int   d_tile_cnt[1100];
__device__ int   d_ntiles;

#define W_SCALE 64.0f
#define W_INV_SCALE 0.015625f

// ---------------- small utility kernels ----------------
__global__ void k_zero_prep() {
    int t = threadIdx.x;
    if (t < 65) d_hist[t] = 0;
    if (t == 65) d_ntiles = 0;
}

// pack w2 into bf16x2 k-pairs: d_w2p[kp][c] = (bf16(w2[2kp][c]), bf16(w2[2kp+1][c]))
__global__ void k_conv_w2(const float* __restrict__ w2) {
    int i = blockIdx.x * 256 + threadIdx.x;   // 32*4096 items
    int kp = i >> 12, c = i & 4095;
    __nv_bfloat162 p = __floats2bfloat162_rn(w2[(size_t)(2 * kp) * 4096 + c],
                                             w2[(size_t)(2 * kp + 1) * 4096 + c]);
    d_w2p[i] = *(uint32_t*)&p;
}

// h = relu(ea @ w1 + b1), packed bf16x2 pairs, computed ONCE per edge
__global__ void k_h(const float* __restrict__ ea,
                    const float* __restrict__ w1, const float* __restrict__ b1, int E) {
    int idx = blockIdx.x * 256 + threadIdx.x;   // E*32 items
    if (idx >= E * 32) return;
    int e = idx >> 5, op = idx & 31;
    const float* ear = ea + (size_t)e * 4;
    float h0 = b1[2 * op], h1 = b1[2 * op + 1];
#pragma unroll
    for (int f = 0; f < 4; f++) {
        h0 = fmaf(ear[f], w1[f * 64 + 2 * op], h0);
        h1 = fmaf(ear[f], w1[f * 64 + 2 * op + 1], h1);
    }
    __nv_bfloat162 p = __floats2bfloat162_rn(fmaxf(h0, 0.f), fmaxf(h1, 0.f));
    d_hp[idx] = *(uint32_t*)&p;
}

__global__ void k_count(const int* __restrict__ ei, int E, float* __restrict__ cnt) {
    int e = blockIdx.x * 256 + threadIdx.x;
    if (e < E) atomicAdd(&cnt[ei[E + e]], 1.0f);
}

// x0 = relu(xin @ w + b), xin [N,F], w [F,64]
__global__ void k_init_x(const float* __restrict__ xin, int F,
                         const float* __restrict__ w, const float* __restrict__ b,
                         int N, float* __restrict__ xout) {
    int idx = blockIdx.x * 256 + threadIdx.x;
    if (idx >= N * 64) return;
    int n = idx >> 6, o = idx & 63;
    const float* xr = xin + (size_t)n * F;
    float acc = b[o];
    for (int f = 0; f < F; f++) acc = fmaf(xr[f], w[f * 64 + o], acc);
    xout[idx] = fmaxf(acc, 0.f);
}

// ---------------- g-branch W build via bf16 mma.sync (m16n8k16), fp8 output ----------------
// R10 geometry: 32 edges x 256 cols; 8 warps = 2 warp_m x 4 warp_n; h preloaded from d_hp.
__global__ void k_build_W_bf16(const float* __restrict__ b2,
                               unsigned char* __restrict__ W) {
    __shared__ uint32_t sh_hp[32][36];         // packed bf16x2 h k-pairs
    __shared__ uint32_t sh_wp[8][264];         // packed bf16x2 w2 slab (8 k-pairs x 256 cols)
    __shared__ unsigned char sh_o[32][256];    // fp8 output stage

    int tid = threadIdx.x;
    int lane = tid & 31, wid = tid >> 5;
    int e0 = blockIdx.y * 32;
    int c0 = blockIdx.x * 256;

    // stage 1: coalesced load of precomputed h-pairs (1024 uint32)
#pragma unroll
    for (int k = 0; k < 4; k++) {
        int idx = k * 256 + tid;
        sh_hp[idx >> 5][idx & 31] = d_hp[(size_t)e0 * 32 + idx];
    }

    int warp_m = wid & 1;
    int warp_n = wid >> 1;
    int gid = lane >> 2, t4 = lane & 3;
    float c[8][4];
#pragma unroll
    for (int j = 0; j < 8; j++)
#pragma unroll
        for (int q = 0; q < 4; q++) c[j][q] = 0.f;

#pragma unroll
    for (int kc = 0; kc < 4; kc++) {           // 4 chunks of k16
        __syncthreads();
#pragma unroll
        for (int k = 0; k < 8; k++) {
            int idx = k * 256 + tid;
            int kp = idx >> 8, cc = idx & 255;
            sh_wp[kp][cc] = d_w2p[(size_t)(kc * 8 + kp) * 4096 + c0 + cc];
        }
        __syncthreads();
        int row = warp_m * 16 + gid;
        uint32_t a0 = sh_hp[row][kc * 8 + t4];
        uint32_t a1 = sh_hp[row + 8][kc * 8 + t4];
        uint32_t a2 = sh_hp[row][kc * 8 + 4 + t4];
        uint32_t a3 = sh_hp[row + 8][kc * 8 + 4 + t4];
#pragma unroll
        for (int j = 0; j < 8; j++) {
            int bn = warp_n * 64 + j * 8 + gid;
            uint32_t b0 = sh_wp[t4][bn];
            uint32_t b1r = sh_wp[t4 + 4][bn];
            asm volatile(
                "mma.sync.aligned.m16n8k16.row.col.f32.bf16.bf16.f32 "
                "{%0,%1,%2,%3}, {%4,%5,%6,%7}, {%8,%9}, {%0,%1,%2,%3};"
                : "+f"(c[j][0]), "+f"(c[j][1]), "+f"(c[j][2]), "+f"(c[j][3])
                : "r"(a0), "r"(a1), "r"(a2), "r"(a3), "r"(b0), "r"(b1r));
        }
    }

    // epilogue: + b2, scale x64, convert to fp8x2, stage in smem
    int r = lane >> 2, q = lane & 3;
#pragma unroll
    for (int j = 0; j < 8; j++) {
        int colL = warp_n * 64 + j * 8 + q * 2;
        float2 bb = *(const float2*)&b2[c0 + colL];
        int rowA = warp_m * 16 + r;
        __nv_fp8x2_storage_t pA = __nv_cvt_float2_to_fp8x2(
            make_float2((c[j][0] + bb.x) * W_SCALE, (c[j][1] + bb.y) * W_SCALE),
            __NV_SATFINITE, __NV_E4M3);
        __nv_fp8x2_storage_t pB = __nv_cvt_float2_to_fp8x2(
            make_float2((c[j][2] + bb.x) * W_SCALE, (c[j][3] + bb.y) * W_SCALE),
            __NV_SATFINITE, __NV_E4M3);
        *(unsigned short*)&sh_o[rowA][colL]     = (unsigned short)pA;
        *(unsigned short*)&sh_o[rowA + 8][colL] = (unsigned short)pB;
    }
    __syncthreads();

    // coalesced copy out: 32 rows x 256B, 16B vectors
    const uint4* src = (const uint4*)&sh_o[0][0];
#pragma unroll
    for (int k = 0; k < 2; k++) {
        int idx = k * 256 + tid;
        int row = idx >> 4, chunk = idx & 15;
        *(uint4*)&W[(size_t)(e0 + row) * 4096 + c0 + chunk * 16] = src[idx];
    }
}

// ---------------- fused msg: g blocks stream fp8 W (full-line loads); lg blocks smem tiles ----------------
__global__ void k_msg_both(const float* __restrict__ xg, const unsigned char* __restrict__ Wg,
                           const int* __restrict__ eig, int Eg, float* __restrict__ aggg, int nbg,
                           const float* __restrict__ xlg, const float* __restrict__ ealg,
                           const int* __restrict__ eilg, int Elg, float* __restrict__ agglg) {
    __shared__ float sC[4096], sD[4096];
    int tid = threadIdx.x;  // 256
    int wid = tid >> 5, lane = tid & 31;

    if ((int)blockIdx.x < nbg) {
        int e = (blockIdx.x * 256 + tid) >> 5;
        if (e >= Eg) return;
        int src = eig[e], tgt = eig[Eg + e];
        int half = lane >> 4, q = lane & 15;
        const unsigned char* Wr = Wg + (size_t)e * 4096;
        const float* xs = xg + (size_t)src * 64;
        float x0 = xs[lane], x1 = xs[lane + 32];
        float a0 = 0.f, a1 = 0.f, a2 = 0.f, a3 = 0.f;
#pragma unroll 8
        for (int jj = 0; jj < 32; jj++) {
            int i = 2 * jj + half;
            float xv = __shfl_sync(0xffffffffu, (jj < 16) ? x0 : x1, 2 * (jj & 15) + half);
            uint32_t w4 = *(const uint32_t*)(Wr + i * 64 + q * 4);
            __half2 lo = __half2(__nv_cvt_fp8x2_to_halfraw2(
                (__nv_fp8x2_storage_t)(w4 & 0xFFFFu), __NV_E4M3));
            __half2 hi = __half2(__nv_cvt_fp8x2_to_halfraw2(
                (__nv_fp8x2_storage_t)(w4 >> 16), __NV_E4M3));
            float2 f0 = __half22float2(lo), f1 = __half22float2(hi);
            a0 = fmaf(xv, f0.x, a0);
            a1 = fmaf(xv, f0.y, a1);
            a2 = fmaf(xv, f1.x, a2);
            a3 = fmaf(xv, f1.y, a3);
        }
        a0 += __shfl_xor_sync(0xffffffffu, a0, 16);
        a1 += __shfl_xor_sync(0xffffffffu, a1, 16);
        a2 += __shfl_xor_sync(0xffffffffu, a2, 16);
        a3 += __shfl_xor_sync(0xffffffffu, a3, 16);
        if (half == 0) {
            float* ag = aggg + (size_t)tgt * 64 + q * 4;
            atomicAdd(ag,     a0 * W_INV_SCALE);
            atomicAdd(ag + 1, a1 * W_INV_SCALE);
            atomicAdd(ag + 2, a2 * W_INV_SCALE);
            atomicAdd(ag + 3, a3 * W_INV_SCALE);
        }
    } else {
        int bt = blockIdx.x - nbg;
        if (bt >= d_ntiles) return;
        int s = d_tile_seg[bt], base = d_tile_base[bt], cnt = d_tile_cnt[bt];
        const float* C = d_C + (size_t)s * 4096;
        const float* Dp = d_D + (size_t)s * 4096;
        for (int i = tid; i < 4096; i += 256) { sC[i] = C[i]; sD[i] = Dp[i]; }
        __syncthreads();
        const float2* C2 = (const float2*)sC;
        const float2* D2 = (const float2*)sD;
#pragma unroll
        for (int p = 0; p < 4; p++) {
            int slotA = p * 16 + wid * 2;
            int slotB = slotA + 1;
            bool vA = slotA < cnt, vB = slotB < cnt;
            int eA = vA ? d_order[base + slotA] : 0;
            int eB = vB ? d_order[base + slotB] : 0;
            int srcA = eilg[eA], tgtA = eilg[Elg + eA];
            int srcB = eilg[eB], tgtB = eilg[Elg + eB];
            float eaA = ealg[eA], eaB = ealg[eB];
            float xA0 = vA ? xlg[(size_t)srcA * 64 + lane] : 0.f;
            float xA1 = vA ? xlg[(size_t)srcA * 64 + lane + 32] : 0.f;
            float xB0 = vB ? xlg[(size_t)srcB * 64 + lane] : 0.f;
            float xB1 = vB ? xlg[(size_t)srcB * 64 + lane + 32] : 0.f;
            float cA0 = 0, cA1 = 0, dA0 = 0, dA1 = 0;
            float cB0 = 0, cB1 = 0, dB0 = 0, dB1 = 0;
#pragma unroll 8
            for (int i = 0; i < 64; i++) {
                float2 cv = C2[i * 32 + lane];
                float2 dv = D2[i * 32 + lane];
                float xa = __shfl_sync(0xffffffffu, (i < 32) ? xA0 : xA1, i & 31);
                float xb = __shfl_sync(0xffffffffu, (i < 32) ? xB0 : xB1, i & 31);
                cA0 = fmaf(xa, cv.x, cA0); cA1 = fmaf(xa, cv.y, cA1);
                dA0 = fmaf(xa, dv.x, dA0); dA1 = fmaf(xa, dv.y, dA1);
                cB0 = fmaf(xb, cv.x, cB0); cB1 = fmaf(xb, cv.y, cB1);
                dB0 = fmaf(xb, dv.x, dB0); dB1 = fmaf(xb, dv.y, dB1);
            }
            if (vA) {
                float* ag = agglg + (size_t)tgtA * 64 + lane * 2;
                atomicAdd(ag,     fmaf(eaA, dA0, cA0));
                atomicAdd(ag + 1, fmaf(eaA, dA1, cA1));
            }
            if (vB) {
                float* ag = agglg + (size_t)tgtB * 64 + lane * 2;
                atomicAdd(ag,     fmaf(eaB, dB0, cB0));
                atomicAdd(ag + 1, fmaf(eaB, dB1, cB1));
            }
        }
    }
}

// ---------------- fused node update ----------------
__global__ void k_update_both(float* __restrict__ xg, const float* __restrict__ rootg,
                              const float* __restrict__ biasg, const float* __restrict__ cntg,
                              float* __restrict__ aggg, int Ng, int nbg,
                              float* __restrict__ xlg, const float* __restrict__ rootlg,
                              const float* __restrict__ biaslg, const float* __restrict__ cntlg,
                              float* __restrict__ agglg, int Nlg) {
    __shared__ float sroot[4096];
    __shared__ float sx[8][64];
    int t = threadIdx.x;  // 512
    int b = blockIdx.x;
    float* x; const float *root, *bias, *cnt; float* agg; int N;
    if (b < nbg) { x = xg; root = rootg; bias = biasg; cnt = cntg; agg = aggg; N = Ng; }
    else { b -= nbg; x = xlg; root = rootlg; bias = biaslg; cnt = cntlg; agg = agglg; N = Nlg; }

    for (int k = t; k < 4096; k += 512) sroot[k] = root[k];
    int nl = t >> 6, o = t & 63;
    int n = b * 8 + nl;
    if (n < N) sx[nl][o] = x[(size_t)n * 64 + o];
    __syncthreads();
    if (n >= N) return;
    float acc = bias[o] + agg[(size_t)n * 64 + o] / fmaxf(cnt[n], 1.0f);
#pragma unroll
    for (int i = 0; i < 64; i++) acc = fmaf(sx[nl][i], sroot[i * 64 + o], acc);
    x[(size_t)n * 64 + o] = fmaxf(acc, 0.f);
    agg[(size_t)n * 64 + o] = 0.f;
}

// ---------------- lg piecewise-linear precompute ----------------
__global__ void k_lg_prep(const float* __restrict__ w1, const float* __restrict__ b1) {
    __shared__ float ts[64];
    __shared__ int cnt;
    int j = threadIdx.x;  // 64
    if (j == 0) cnt = 0;
    __syncthreads();
    float w = w1[j], b = b1[j];
    if (w != 0.f) {
        float t = -b / w;
        if (t > 0.f && t < 1.f) {
            int p = atomicAdd(&cnt, 1);
            ts[p] = t;
        }
    }
    __syncthreads();
    if (j == 0) {
        for (int i = 1; i < cnt; i++) {
            float v = ts[i];
            int k = i;
            while (k > 0 && ts[k - 1] > v) { ts[k] = ts[k - 1]; k--; }
            ts[k] = v;
        }
        d_m = cnt;
        for (int i = 0; i < cnt; i++) d_T[i] = ts[i];
    }
}

__global__ void k_lg_tables(const float* __restrict__ w1, const float* __restrict__ b1,
                            const float* __restrict__ w2, const float* __restrict__ b2) {
    int s = blockIdx.x;
    int m = d_m;
    if (s > m) return;
    float lo = (s == 0) ? 0.f : d_T[s - 1];
    float hi = (s == m) ? 1.f : d_T[s];
    float mid = 0.5f * (lo + hi);
    __shared__ float cb[64], cw[64];
    int t = threadIdx.x;  // 256
    if (t < 64) {
        float w = w1[t], b = b1[t];
        bool act = (fmaf(w, mid, b) > 0.f);
        cb[t] = act ? b : 0.f;
        cw[t] = act ? w : 0.f;
    }
    __syncthreads();
    for (int io = t; io < 4096; io += 256) {
        float c = b2[io], d = 0.f;
#pragma unroll 8
        for (int j = 0; j < 64; j++) {
            float wv = w2[(size_t)j * 4096 + io];
            c = fmaf(cb[j], wv, c);
            d = fmaf(cw[j], wv, d);
        }
        d_C[(size_t)s * 4096 + io] = c;
        d_D[(size_t)s * 4096 + io] = d;
    }
}

__global__ void k_lg_seg(const float* __restrict__ ea, int E) {
    int e = blockIdx.x * 256 + threadIdx.x;
    if (e >= E) return;
    float v = ea[e];
    int lo = 0, hi = d_m;
    while (lo < hi) {
        int mid = (lo + hi) >> 1;
        if (d_T[mid] <= v) lo = mid + 1; else hi = mid;
    }
    d_seg[e] = lo;
    atomicAdd(&d_hist[lo], 1);
}

__global__ void k_lg_scan() {
    __shared__ int soff[66], stbase[66], shist[65];
    int ns = d_m + 1;
    int t = threadIdx.x;  // 128
    if (t < ns) shist[t] = d_hist[t];
    __syncthreads();
    if (t == 0) {
        int off = 0, tb = 0;
        for (int s = 0; s < ns; s++) {
            soff[s] = off;
            stbase[s] = tb;
            off += shist[s];
            tb += (shist[s] + 63) >> 6;
        }
        d_ntiles = tb;
    }
    __syncthreads();
    for (int s = t; s < ns; s += blockDim.x) {
        d_cur[s] = soff[s];
        int h = shist[s];
        int nt = (h + 63) >> 6;
        for (int k = 0; k < nt; k++) {
            int idx = stbase[s] + k;
            d_tile_seg[idx] = s;
            d_tile_base[idx] = soff[s] + k * 64;
            d_tile_cnt[idx] = min(64, h - k * 64);
        }
    }
}

__global__ void k_lg_scatter(int E) {
    int e = blockIdx.x * 256 + threadIdx.x;
    if (e >= E) return;
    int s = d_seg[e];
    int p = atomicAdd(&d_cur[s], 1);
    d_order[p] = e;
}

// ---------------- fused sum pooling ----------------
__global__ void k_pool_both(const float* __restrict__ xg, int Ng,
                            const float* __restrict__ xlg, int Nlg,
                            float* __restrict__ out) {
    __shared__ float sh[256];
    int t = threadIdx.x;
    int o = t & 63, g = t >> 6;
    const float* x; int N; float* op;
    int b = blockIdx.x;
    if (b < 120) { x = xg; N = Ng; op = out; }
    else { b -= 120; x = xlg; N = Nlg; op = out + 64; }
    float acc = 0.f;
#pragma unroll 4
    for (int n = b * 4 + g; n < N; n += 120 * 4)
        acc += x[(size_t)n * 64 + o];
    sh[t] = acc;
    __syncthreads();
    if (g == 0)
        atomicAdd(&op[o], sh[o] + sh[64 + o] + sh[128 + o] + sh[192 + o]);
}

// ---------------- head MLP ----------------
__global__ void k_head(const float* __restrict__ adduct,
                       const float* __restrict__ bw, const float* __restrict__ bb,
                       const float* __restrict__ l1w, const float* __restrict__ l1b,
                       const float* __restrict__ l2w, const float* __restrict__ l2b,
                       float* __restrict__ out) {
    __shared__ float a[384];
    __shared__ float red[384];
    int t = threadIdx.x;  // 384
    float acc = bb[t];
#pragma unroll 8
    for (int i = 0; i < 128; i++) acc = fmaf(d_feat[i], bw[i * 384 + t], acc);
    for (int k = 0; k < 3; k++) acc = fmaf(adduct[k], bw[(128 + k) * 384 + t], acc);
    a[t] = fmaxf(acc, 0.f);
    __syncthreads();
    for (int l = 0; l < 6; l++) {
        float s = l1b[t];
#pragma unroll 8
        for (int i = 0; i < 384; i++) s = fmaf(a[i], l1w[i * 384 + t], s);
        __syncthreads();
        a[t] = fmaxf(s, 0.f);
        __syncthreads();
    }
    red[t] = a[t] * l2w[t];
    __syncthreads();
    for (int s = 192; s >= 6; s >>= 1) {
        if (t < s) red[t] += red[t + s];
        __syncthreads();
    }
    if (t == 0)
        out[0] = red[0] + red[1] + red[2] + red[3] + red[4] + red[5] + l2b[0];
}

// ---------------- launch ----------------
extern "C" void kernel_launch(void* const* d_in, const int* in_sizes, int n_in,
                              void* d_out, int out_size) {
    const float* gx       = (const float*)d_in[0];
    const int*   g_ei     = (const int*)  d_in[1];
    const float* g_ea     = (const float*)d_in[2];
    const float* lgx      = (const float*)d_in[3];
    const int*   lg_ei    = (const int*)  d_in[4];
    const float* lg_ea    = (const float*)d_in[5];
    const float* adduct   = (const float*)d_in[6];
    const float* lin0_w   = (const float*)d_in[7];
    const float* lin0_b   = (const float*)d_in[8];
    const float* g_w1     = (const float*)d_in[9];
    const float* g_b1     = (const float*)d_in[10];
    const float* g_w2     = (const float*)d_in[11];
    const float* g_b2     = (const float*)d_in[12];
    const float* g_root   = (const float*)d_in[13];
    const float* g_bias   = (const float*)d_in[14];
    const float* lin0lg_w = (const float*)d_in[15];
    const float* lin0lg_b = (const float*)d_in[16];
    const float* lg_w1    = (const float*)d_in[17];
    const float* lg_b1    = (const float*)d_in[18];
    const float* lg_w2    = (const float*)d_in[19];
    const float* lg_b2    = (const float*)d_in[20];
    const float* lg_root  = (const float*)d_in[21];
    const float* lg_bias  = (const float*)d_in[22];
    const float* bott_w   = (const float*)d_in[23];
    const float* bott_b   = (const float*)d_in[24];
    const float* lin1_w   = (const float*)d_in[25];
    const float* lin1_b   = (const float*)d_in[26];
    const float* lin2_w   = (const float*)d_in[27];
    const float* lin2_b   = (const float*)d_in[28];

    const int N_G = 30000, E_G = 60000, N_LG = 60000, E_LG = 60000;

    unsigned char* W_g;
    float *x_g, *x_lg, *agg_g, *agg_lg, *cnt_g, *cnt_lg, *feat;
    cudaGetSymbolAddress((void**)&W_g,    d_W_g);
    cudaGetSymbolAddress((void**)&x_g,    d_x_g);
    cudaGetSymbolAddress((void**)&x_lg,   d_x_lg);
    cudaGetSymbolAddress((void**)&agg_g,  d_agg_g);
    cudaGetSymbolAddress((void**)&agg_lg, d_agg_lg);
    cudaGetSymbolAddress((void**)&cnt_g,  d_cnt_g);
    cudaGetSymbolAddress((void**)&cnt_lg, d_cnt_lg);
    cudaGetSymbolAddress((void**)&feat,   d_feat);

    // side stream + fork/join events
    cudaStream_t s2;
    cudaStreamCreateWithFlags(&s2, cudaStreamNonBlocking);
    cudaEvent_t evFork, evJoin;
    cudaEventCreateWithFlags(&evFork, cudaEventDisableTiming);
    cudaEventCreateWithFlags(&evJoin, cudaEventDisableTiming);

    // zero scratch (async memsets; not kernel launches)
    cudaMemsetAsync(agg_g,  0, (size_t)N_G  * 64 * sizeof(float));
    cudaMemsetAsync(agg_lg, 0, (size_t)N_LG * 64 * sizeof(float));
    cudaMemsetAsync(cnt_g,  0, N_G  * sizeof(float));
    cudaMemsetAsync(cnt_lg, 0, N_LG * sizeof(float));
    cudaMemsetAsync(feat,   0, 128 * sizeof(float));
    cudaEventRecord(evFork, 0);

    // main stream: conv(1), h(2), count(3), BUILD(4) -> ncu target
    k_conv_w2<<<(32 * 4096) / 256, 256>>>(g_w2);
    k_h<<<(E_G * 32 + 255) / 256, 256>>>(g_ea, g_w1, g_b1, E_G);
    k_count<<<(E_G + 255) / 256, 256>>>(g_ei, E_G, cnt_g);
    dim3 gw(4096 / 256, E_G / 32);
    k_build_W_bf16<<<gw, 256>>>(g_b2, W_g);

    // side stream: second count + inits + lg prep, overlapped with build
    cudaStreamWaitEvent(s2, evFork, 0);
    k_count<<<(E_LG + 255) / 256, 256, 0, s2>>>(lg_ei, E_LG, cnt_lg);
    k_init_x<<<(N_G * 64 + 255) / 256, 256, 0, s2>>>(gx, 20, lin0_w, lin0_b, N_G, x_g);
    k_init_x<<<(N_LG * 64 + 255) / 256, 256, 0, s2>>>(lgx, 5, lin0lg_w, lin0lg_b, N_LG, x_lg);
    k_zero_prep<<<1, 128, 0, s2>>>();
    k_lg_prep<<<1, 64, 0, s2>>>(lg_w1, lg_b1);
    k_lg_tables<<<65, 256, 0, s2>>>(lg_w1, lg_b1, lg_w2, lg_b2);
    k_lg_seg<<<(E_LG + 255) / 256, 256, 0, s2>>>(lg_ea, E_LG);
    k_lg_scan<<<1, 128, 0, s2>>>();
    k_lg_scatter<<<(E_LG + 255) / 256, 256, 0, s2>>>(E_LG);
    cudaEventRecord(evJoin, s2);
    cudaStreamWaitEvent(0, evJoin, 0);

    // 3 NNConv iterations, g+lg fused per phase
    const int nbg_msg = E_G / 8;
    const int lg_tiles_max = ((E_LG / 64 + 66) + 31) & ~31;
    const int nbg_upd = (N_G + 7) / 8;
    const int nblg_upd = (N_LG + 7) / 8;
    for (int it = 0; it < 3; it++) {
        k_msg_both<<<nbg_msg + lg_tiles_max, 256>>>(
            x_g, W_g, g_ei, E_G, agg_g, nbg_msg,
            x_lg, lg_ea, lg_ei, E_LG, agg_lg);
        k_update_both<<<nbg_upd + nblg_upd, 512>>>(
            x_g, g_root, g_bias, cnt_g, agg_g, N_G, nbg_upd,
            x_lg, lg_root, lg_bias, cnt_lg, agg_lg, N_LG);
    }

    // fused sum pooling
    k_pool_both<<<240, 256>>>(x_g, N_G, x_lg, N_LG, feat);

    // head MLP -> scalar
    k_head<<<1, 384>>>(adduct, bott_w, bott_b, lin1_w, lin1_b, lin2_w, lin2_b,
                       (float*)d_out);
}

// round 14
// speedup vs baseline: 1.1670x; 1.0625x over previous
#include <cuda_runtime.h>
#include <cuda_bf16.h>
#include <cuda_fp8.h>
#include <cstddef>
#include <cstdint>

// ---------------- scratch (device globals: allocation-free) ----------------
__device__ unsigned char d_W_g [(size_t)60000 * 4096];  // per-edge [64,64] weights (e4m3, x64 scale)
__device__ uint32_t d_w2p [(size_t)32 * 4096];          // bf16x2-packed g_w2 k-pairs
__device__ uint32_t d_hp  [(size_t)60000 * 32];         // bf16x2-packed h k-pairs per edge
__device__ float d_x_g  [(size_t)30000 * 64];
__device__ float d_x_lg [(size_t)60000 * 64];
__device__ float d_agg_g [(size_t)30000 * 64];
__device__ float d_agg_lg[(size_t)60000 * 64];
__device__ float d_dummy [(size_t)30000 * 64];          // sink for the profiled dummy msg launch
__device__ float d_cnt_g [30000];
__device__ float d_cnt_lg[60000];
__device__ float d_feat[128];

// lg piecewise-linear machinery
__device__ float d_T[64];
__device__ int   d_m;
__device__ float d_C[(size_t)65 * 4096];
__device__ float d_D[(size_t)65 * 4096];
__device__ int   d_seg[60000];
__device__ int   d_hist[65];
__device__ int   d_cur[65];
__device__ int   d_order[60000];
__device__ int   d_tile_seg[1100];
__device__ int   d_tile_base[1100];
__device__ int   d_tile_cnt[1100];
__device__ int   d_ntiles;

#define W_SCALE 64.0f
#define W_INV_SCALE 0.015625f

// ---------------- small utility kernels ----------------
__global__ void k_zero_prep() {
    int t = threadIdx.x;
    if (t < 65) d_hist[t] = 0;
    if (t == 65) d_ntiles = 0;
}

// pack w2 into bf16x2 k-pairs: d_w2p[kp][c] = (bf16(w2[2kp][c]), bf16(w2[2kp+1][c]))
__global__ void k_conv_w2(const float* __restrict__ w2) {
    int i = blockIdx.x * 256 + threadIdx.x;   // 32*4096 items
    int kp = i >> 12, c = i & 4095;
    __nv_bfloat162 p = __floats2bfloat162_rn(w2[(size_t)(2 * kp) * 4096 + c],
                                             w2[(size_t)(2 * kp + 1) * 4096 + c]);
    d_w2p[i] = *(uint32_t*)&p;
}

// h = relu(ea @ w1 + b1), packed bf16x2 pairs, computed ONCE per edge
__global__ void k_h(const float* __restrict__ ea,
                    const float* __restrict__ w1, const float* __restrict__ b1, int E) {
    int idx = blockIdx.x * 256 + threadIdx.x;   // E*32 items
    if (idx >= E * 32) return;
    int e = idx >> 5, op = idx & 31;
    const float* ear = ea + (size_t)e * 4;
    float h0 = b1[2 * op], h1 = b1[2 * op + 1];
#pragma unroll
    for (int f = 0; f < 4; f++) {
        h0 = fmaf(ear[f], w1[f * 64 + 2 * op], h0);
        h1 = fmaf(ear[f], w1[f * 64 + 2 * op + 1], h1);
    }
    __nv_bfloat162 p = __floats2bfloat162_rn(fmaxf(h0, 0.f), fmaxf(h1, 0.f));
    d_hp[idx] = *(uint32_t*)&p;
}

__global__ void k_count(const int* __restrict__ ei, int E, float* __restrict__ cnt) {
    int e = blockIdx.x * 256 + threadIdx.x;
    if (e < E) atomicAdd(&cnt[ei[E + e]], 1.0f);
}

// x0 = relu(xin @ w + b), xin [N,F], w [F,64]
__global__ void k_init_x(const float* __restrict__ xin, int F,
                         const float* __restrict__ w, const float* __restrict__ b,
                         int N, float* __restrict__ xout) {
    int idx = blockIdx.x * 256 + threadIdx.x;
    if (idx >= N * 64) return;
    int n = idx >> 6, o = idx & 63;
    const float* xr = xin + (size_t)n * F;
    float acc = b[o];
    for (int f = 0; f < F; f++) acc = fmaf(xr[f], w[f * 64 + o], acc);
    xout[idx] = fmaxf(acc, 0.f);
}

// ---------------- g-branch W build: persistent w2 slab, 15 edge-tiles per block ----------------
// grid (16 col-blocks, 125 edge-groups); block stages its 32KB w2 slab ONCE,
// loops 15 tiles of 32 edges (125*15*32 = 60000 exactly).
__global__ void k_build_W_bf16(const float* __restrict__ b2,
                               unsigned char* __restrict__ W) {
    __shared__ uint32_t sh_wp[32][264];        // full w2 column slab (32 k-pairs x 256 cols)
    __shared__ uint32_t sh_hp[32][36];         // packed bf16x2 h k-pairs per tile
    __shared__ unsigned char sh_o[32][256];    // fp8 output stage

    int tid = threadIdx.x;
    int lane = tid & 31, wid = tid >> 5;
    int c0 = blockIdx.x * 256;

    // stage full w2 slab once (8192 words, 32/thread)
#pragma unroll
    for (int k = 0; k < 32; k++) {
        int idx = k * 256 + tid;
        int kp = idx >> 8, cc = idx & 255;
        sh_wp[kp][cc] = d_w2p[(size_t)kp * 4096 + c0 + cc];
    }

    int warp_m = wid & 1;
    int warp_n = wid >> 1;
    int gid = lane >> 2, t4 = lane & 3;
    int r = lane >> 2, q = lane & 3;

    for (int t = 0; t < 15; t++) {
        int e0 = (blockIdx.y * 15 + t) * 32;
        __syncthreads();   // prev copy-out done; (t=0: no-op ordering)
#pragma unroll
        for (int k = 0; k < 4; k++) {
            int idx = k * 256 + tid;
            sh_hp[idx >> 5][idx & 31] = d_hp[(size_t)e0 * 32 + idx];
        }
        __syncthreads();   // h ready (also covers the one-time w2 staging)

        float c[8][4];
#pragma unroll
        for (int j = 0; j < 8; j++)
#pragma unroll
            for (int qq = 0; qq < 4; qq++) c[j][qq] = 0.f;

#pragma unroll
        for (int kc = 0; kc < 4; kc++) {
            int row = warp_m * 16 + gid;
            uint32_t a0 = sh_hp[row][kc * 8 + t4];
            uint32_t a1 = sh_hp[row + 8][kc * 8 + t4];
            uint32_t a2 = sh_hp[row][kc * 8 + 4 + t4];
            uint32_t a3 = sh_hp[row + 8][kc * 8 + 4 + t4];
#pragma unroll
            for (int j = 0; j < 8; j++) {
                int bn = warp_n * 64 + j * 8 + gid;
                uint32_t b0 = sh_wp[kc * 8 + t4][bn];
                uint32_t b1r = sh_wp[kc * 8 + t4 + 4][bn];
                asm volatile(
                    "mma.sync.aligned.m16n8k16.row.col.f32.bf16.bf16.f32 "
                    "{%0,%1,%2,%3}, {%4,%5,%6,%7}, {%8,%9}, {%0,%1,%2,%3};"
                    : "+f"(c[j][0]), "+f"(c[j][1]), "+f"(c[j][2]), "+f"(c[j][3])
                    : "r"(a0), "r"(a1), "r"(a2), "r"(a3), "r"(b0), "r"(b1r));
            }
        }

        // epilogue: + b2, scale x64, fp8x2, stage in smem
#pragma unroll
        for (int j = 0; j < 8; j++) {
            int colL = warp_n * 64 + j * 8 + q * 2;
            float2 bb = *(const float2*)&b2[c0 + colL];
            int rowA = warp_m * 16 + r;
            __nv_fp8x2_storage_t pA = __nv_cvt_float2_to_fp8x2(
                make_float2((c[j][0] + bb.x) * W_SCALE, (c[j][1] + bb.y) * W_SCALE),
                __NV_SATFINITE, __NV_E4M3);
            __nv_fp8x2_storage_t pB = __nv_cvt_float2_to_fp8x2(
                make_float2((c[j][2] + bb.x) * W_SCALE, (c[j][3] + bb.y) * W_SCALE),
                __NV_SATFINITE, __NV_E4M3);
            *(unsigned short*)&sh_o[rowA][colL]     = (unsigned short)pA;
            *(unsigned short*)&sh_o[rowA + 8][colL] = (unsigned short)pB;
        }
        __syncthreads();   // sh_o ready, sh_hp consumed

        // coalesced copy out: 32 rows x 256B, 16B vectors
        const uint4* src = (const uint4*)&sh_o[0][0];
#pragma unroll
        for (int k = 0; k < 2; k++) {
            int idx = k * 256 + tid;
            int row = idx >> 4, chunk = idx & 15;
            *(uint4*)&W[(size_t)(e0 + row) * 4096 + c0 + chunk * 16] = src[idx];
        }
    }
}

// ---------------- fused msg: g blocks stream fp8 W (full-line loads); lg blocks smem tiles ----------------
__global__ void k_msg_both(const float* __restrict__ xg, const unsigned char* __restrict__ Wg,
                           const int* __restrict__ eig, int Eg, float* __restrict__ aggg, int nbg,
                           const float* __restrict__ xlg, const float* __restrict__ ealg,
                           const int* __restrict__ eilg, int Elg, float* __restrict__ agglg) {
    __shared__ float sC[4096], sD[4096];
    int tid = threadIdx.x;  // 256
    int wid = tid >> 5, lane = tid & 31;

    if ((int)blockIdx.x < nbg) {
        int e = (blockIdx.x * 256 + tid) >> 5;
        if (e >= Eg) return;
        int src = eig[e], tgt = eig[Eg + e];
        int half = lane >> 4, q = lane & 15;
        const unsigned char* Wr = Wg + (size_t)e * 4096;
        const float* xs = xg + (size_t)src * 64;
        float x0 = xs[lane], x1 = xs[lane + 32];
        float a0 = 0.f, a1 = 0.f, a2 = 0.f, a3 = 0.f;
#pragma unroll 8
        for (int jj = 0; jj < 32; jj++) {
            int i = 2 * jj + half;
            float xv = __shfl_sync(0xffffffffu, (jj < 16) ? x0 : x1, 2 * (jj & 15) + half);
            uint32_t w4 = *(const uint32_t*)(Wr + i * 64 + q * 4);
            __half2 lo = __half2(__nv_cvt_fp8x2_to_halfraw2(
                (__nv_fp8x2_storage_t)(w4 & 0xFFFFu), __NV_E4M3));
            __half2 hi = __half2(__nv_cvt_fp8x2_to_halfraw2(
                (__nv_fp8x2_storage_t)(w4 >> 16), __NV_E4M3));
            float2 f0 = __half22float2(lo), f1 = __half22float2(hi);
            a0 = fmaf(xv, f0.x, a0);
            a1 = fmaf(xv, f0.y, a1);
            a2 = fmaf(xv, f1.x, a2);
            a3 = fmaf(xv, f1.y, a3);
        }
        a0 += __shfl_xor_sync(0xffffffffu, a0, 16);
        a1 += __shfl_xor_sync(0xffffffffu, a1, 16);
        a2 += __shfl_xor_sync(0xffffffffu, a2, 16);
        a3 += __shfl_xor_sync(0xffffffffu, a3, 16);
        if (half == 0) {
            float* ag = aggg + (size_t)tgt * 64 + q * 4;
            atomicAdd(ag,     a0 * W_INV_SCALE);
            atomicAdd(ag + 1, a1 * W_INV_SCALE);
            atomicAdd(ag + 2, a2 * W_INV_SCALE);
            atomicAdd(ag + 3, a3 * W_INV_SCALE);
        }
    } else {
        int bt = blockIdx.x - nbg;
        if (bt >= d_ntiles) return;
        int s = d_tile_seg[bt], base = d_tile_base[bt], cnt = d_tile_cnt[bt];
        const float* C = d_C + (size_t)s * 4096;
        const float* Dp = d_D + (size_t)s * 4096;
        for (int i = tid; i < 4096; i += 256) { sC[i] = C[i]; sD[i] = Dp[i]; }
        __syncthreads();
        const float2* C2 = (const float2*)sC;
        const float2* D2 = (const float2*)sD;
#pragma unroll
        for (int p = 0; p < 4; p++) {
            int slotA = p * 16 + wid * 2;
            int slotB = slotA + 1;
            bool vA = slotA < cnt, vB = slotB < cnt;
            int eA = vA ? d_order[base + slotA] : 0;
            int eB = vB ? d_order[base + slotB] : 0;
            int srcA = eilg[eA], tgtA = eilg[Elg + eA];
            int srcB = eilg[eB], tgtB = eilg[Elg + eB];
            float eaA = ealg[eA], eaB = ealg[eB];
            float xA0 = vA ? xlg[(size_t)srcA * 64 + lane] : 0.f;
            float xA1 = vA ? xlg[(size_t)srcA * 64 + lane + 32] : 0.f;
            float xB0 = vB ? xlg[(size_t)srcB * 64 + lane] : 0.f;
            float xB1 = vB ? xlg[(size_t)srcB * 64 + lane + 32] : 0.f;
            float cA0 = 0, cA1 = 0, dA0 = 0, dA1 = 0;
            float cB0 = 0, cB1 = 0, dB0 = 0, dB1 = 0;
#pragma unroll 8
            for (int i = 0; i < 64; i++) {
                float2 cv = C2[i * 32 + lane];
                float2 dv = D2[i * 32 + lane];
                float xa = __shfl_sync(0xffffffffu, (i < 32) ? xA0 : xA1, i & 31);
                float xb = __shfl_sync(0xffffffffu, (i < 32) ? xB0 : xB1, i & 31);
                cA0 = fmaf(xa, cv.x, cA0); cA1 = fmaf(xa, cv.y, cA1);
                dA0 = fmaf(xa, dv.x, dA0); dA1 = fmaf(xa, dv.y, dA1);
                cB0 = fmaf(xb, cv.x, cB0); cB1 = fmaf(xb, cv.y, cB1);
                dB0 = fmaf(xb, dv.x, dB0); dB1 = fmaf(xb, dv.y, dB1);
            }
            if (vA) {
                float* ag = agglg + (size_t)tgtA * 64 + lane * 2;
                atomicAdd(ag,     fmaf(eaA, dA0, cA0));
                atomicAdd(ag + 1, fmaf(eaA, dA1, cA1));
            }
            if (vB) {
                float* ag = agglg + (size_t)tgtB * 64 + lane * 2;
                atomicAdd(ag,     fmaf(eaB, dB0, cB0));
                atomicAdd(ag + 1, fmaf(eaB, dB1, cB1));
            }
        }
    }
}

// ---------------- fused node update ----------------
__global__ void k_update_both(float* __restrict__ xg, const float* __restrict__ rootg,
                              const float* __restrict__ biasg, const float* __restrict__ cntg,
                              float* __restrict__ aggg, int Ng, int nbg,
                              float* __restrict__ xlg, const float* __restrict__ rootlg,
                              const float* __restrict__ biaslg, const float* __restrict__ cntlg,
                              float* __restrict__ agglg, int Nlg) {
    __shared__ float sroot[4096];
    __shared__ float sx[8][64];
    int t = threadIdx.x;  // 512
    int b = blockIdx.x;
    float* x; const float *root, *bias, *cnt; float* agg; int N;
    if (b < nbg) { x = xg; root = rootg; bias = biasg; cnt = cntg; agg = aggg; N = Ng; }
    else { b -= nbg; x = xlg; root = rootlg; bias = biaslg; cnt = cntlg; agg = agglg; N = Nlg; }

    for (int k = t; k < 4096; k += 512) sroot[k] = root[k];
    int nl = t >> 6, o = t & 63;
    int n = b * 8 + nl;
    if (n < N) sx[nl][o] = x[(size_t)n * 64 + o];
    __syncthreads();
    if (n >= N) return;
    float acc = bias[o] + agg[(size_t)n * 64 + o] / fmaxf(cnt[n], 1.0f);
#pragma unroll
    for (int i = 0; i < 64; i++) acc = fmaf(sx[nl][i], sroot[i * 64 + o], acc);
    x[(size_t)n * 64 + o] = fmaxf(acc, 0.f);
    agg[(size_t)n * 64 + o] = 0.f;
}

// ---------------- lg piecewise-linear precompute ----------------
__global__ void k_lg_prep(const float* __restrict__ w1, const float* __restrict__ b1) {
    __shared__ float ts[64];
    __shared__ int cnt;
    int j = threadIdx.x;  // 64
    if (j == 0) cnt = 0;
    __syncthreads();
    float w = w1[j], b = b1[j];
    if (w != 0.f) {
        float t = -b / w;
        if (t > 0.f && t < 1.f) {
            int p = atomicAdd(&cnt, 1);
            ts[p] = t;
        }
    }
    __syncthreads();
    if (j == 0) {
        for (int i = 1; i < cnt; i++) {
            float v = ts[i];
            int k = i;
            while (k > 0 && ts[k - 1] > v) { ts[k] = ts[k - 1]; k--; }
            ts[k] = v;
        }
        d_m = cnt;
        for (int i = 0; i < cnt; i++) d_T[i] = ts[i];
    }
}

__global__ void k_lg_tables(const float* __restrict__ w1, const float* __restrict__ b1,
                            const float* __restrict__ w2, const float* __restrict__ b2) {
    int s = blockIdx.x;
    int m = d_m;
    if (s > m) return;
    float lo = (s == 0) ? 0.f : d_T[s - 1];
    float hi = (s == m) ? 1.f : d_T[s];
    float mid = 0.5f * (lo + hi);
    __shared__ float cb[64], cw[64];
    int t = threadIdx.x;  // 256
    if (t < 64) {
        float w = w1[t], b = b1[t];
        bool act = (fmaf(w, mid, b) > 0.f);
        cb[t] = act ? b : 0.f;
        cw[t] = act ? w : 0.f;
    }
    __syncthreads();
    for (int io = t; io < 4096; io += 256) {
        float c = b2[io], d = 0.f;
#pragma unroll 8
        for (int j = 0; j < 64; j++) {
            float wv = w2[(size_t)j * 4096 + io];
            c = fmaf(cb[j], wv, c);
            d = fmaf(cw[j], wv, d);
        }
        d_C[(size_t)s * 4096 + io] = c;
        d_D[(size_t)s * 4096 + io] = d;
    }
}

__global__ void k_lg_seg(const float* __restrict__ ea, int E) {
    int e = blockIdx.x * 256 + threadIdx.x;
    if (e >= E) return;
    float v = ea[e];
    int lo = 0, hi = d_m;
    while (lo < hi) {
        int mid = (lo + hi) >> 1;
        if (d_T[mid] <= v) lo = mid + 1; else hi = mid;
    }
    d_seg[e] = lo;
    atomicAdd(&d_hist[lo], 1);
}

__global__ void k_lg_scan() {
    __shared__ int soff[66], stbase[66], shist[65];
    int ns = d_m + 1;
    int t = threadIdx.x;  // 128
    if (t < ns) shist[t] = d_hist[t];
    __syncthreads();
    if (t == 0) {
        int off = 0, tb = 0;
        for (int s = 0; s < ns; s++) {
            soff[s] = off;
            stbase[s] = tb;
            off += shist[s];
            tb += (shist[s] + 63) >> 6;
        }
        d_ntiles = tb;
    }
    __syncthreads();
    for (int s = t; s < ns; s += blockDim.x) {
        d_cur[s] = soff[s];
        int h = shist[s];
        int nt = (h + 63) >> 6;
        for (int k = 0; k < nt; k++) {
            int idx = stbase[s] + k;
            d_tile_seg[idx] = s;
            d_tile_base[idx] = soff[s] + k * 64;
            d_tile_cnt[idx] = min(64, h - k * 64);
        }
    }
}

__global__ void k_lg_scatter(int E) {
    int e = blockIdx.x * 256 + threadIdx.x;
    if (e >= E) return;
    int s = d_seg[e];
    int p = atomicAdd(&d_cur[s], 1);
    d_order[p] = e;
}

// ---------------- fused sum pooling ----------------
__global__ void k_pool_both(const float* __restrict__ xg, int Ng,
                            const float* __restrict__ xlg, int Nlg,
                            float* __restrict__ out) {
    __shared__ float sh[256];
    int t = threadIdx.x;
    int o = t & 63, g = t >> 6;
    const float* x; int N; float* op;
    int b = blockIdx.x;
    if (b < 120) { x = xg; N = Ng; op = out; }
    else { b -= 120; x = xlg; N = Nlg; op = out + 64; }
    float acc = 0.f;
#pragma unroll 4
    for (int n = b * 4 + g; n < N; n += 120 * 4)
        acc += x[(size_t)n * 64 + o];
    sh[t] = acc;
    __syncthreads();
    if (g == 0)
        atomicAdd(&op[o], sh[o] + sh[64 + o] + sh[128 + o] + sh[192 + o]);
}

// ---------------- head MLP ----------------
__global__ void k_head(const float* __restrict__ adduct,
                       const float* __restrict__ bw, const float* __restrict__ bb,
                       const float* __restrict__ l1w, const float* __restrict__ l1b,
                       const float* __restrict__ l2w, const float* __restrict__ l2b,
                       float* __restrict__ out) {
    __shared__ float a[384];
    __shared__ float red[384];
    int t = threadIdx.x;  // 384
    float acc = bb[t];
#pragma unroll 8
    for (int i = 0; i < 128; i++) acc = fmaf(d_feat[i], bw[i * 384 + t], acc);
    for (int k = 0; k < 3; k++) acc = fmaf(adduct[k], bw[(128 + k) * 384 + t], acc);
    a[t] = fmaxf(acc, 0.f);
    __syncthreads();
    for (int l = 0; l < 6; l++) {
        float s = l1b[t];
#pragma unroll 8
        for (int i = 0; i < 384; i++) s = fmaf(a[i], l1w[i * 384 + t], s);
        __syncthreads();
        a[t] = fmaxf(s, 0.f);
        __syncthreads();
    }
    red[t] = a[t] * l2w[t];
    __syncthreads();
    for (int s = 192; s >= 6; s >>= 1) {
        if (t < s) red[t] += red[t + s];
        __syncthreads();
    }
    if (t == 0)
        out[0] = red[0] + red[1] + red[2] + red[3] + red[4] + red[5] + l2b[0];
}

// ---------------- launch ----------------
extern "C" void kernel_launch(void* const* d_in, const int* in_sizes, int n_in,
                              void* d_out, int out_size) {
    const float* gx       = (const float*)d_in[0];
    const int*   g_ei     = (const int*)  d_in[1];
    const float* g_ea     = (const float*)d_in[2];
    const float* lgx      = (const float*)d_in[3];
    const int*   lg_ei    = (const int*)  d_in[4];
    const float* lg_ea    = (const float*)d_in[5];
    const float* adduct   = (const float*)d_in[6];
    const float* lin0_w   = (const float*)d_in[7];
    const float* lin0_b   = (const float*)d_in[8];
    const float* g_w1     = (const float*)d_in[9];
    const float* g_b1     = (const float*)d_in[10];
    const float* g_w2     = (const float*)d_in[11];
    const float* g_b2     = (const float*)d_in[12];
    const float* g_root   = (const float*)d_in[13];
    const float* g_bias   = (const float*)d_in[14];
    const float* lin0lg_w = (const float*)d_in[15];
    const float* lin0lg_b = (const float*)d_in[16];
    const float* lg_w1    = (const float*)d_in[17];
    const float* lg_b1    = (const float*)d_in[18];
    const float* lg_w2    = (const float*)d_in[19];
    const float* lg_b2    = (const float*)d_in[20];
    const float* lg_root  = (const float*)d_in[21];
    const float* lg_bias  = (const float*)d_in[22];
    const float* bott_w   = (const float*)d_in[23];
    const float* bott_b   = (const float*)d_in[24];
    const float* lin1_w   = (const float*)d_in[25];
    const float* lin1_b   = (const float*)d_in[26];
    const float* lin2_w   = (const float*)d_in[27];
    const float* lin2_b   = (const float*)d_in[28];

    const int N_G = 30000, E_G = 60000, N_LG = 60000, E_LG = 60000;

    unsigned char* W_g;
    float *x_g, *x_lg, *agg_g, *agg_lg, *cnt_g, *cnt_lg, *feat, *dummy;
    cudaGetSymbolAddress((void**)&W_g,    d_W_g);
    cudaGetSymbolAddress((void**)&x_g,    d_x_g);
    cudaGetSymbolAddress((void**)&x_lg,   d_x_lg);
    cudaGetSymbolAddress((void**)&agg_g,  d_agg_g);
    cudaGetSymbolAddress((void**)&agg_lg, d_agg_lg);
    cudaGetSymbolAddress((void**)&cnt_g,  d_cnt_g);
    cudaGetSymbolAddress((void**)&cnt_lg, d_cnt_lg);
    cudaGetSymbolAddress((void**)&feat,   d_feat);
    cudaGetSymbolAddress((void**)&dummy,  d_dummy);

    // side stream + fork/join events
    cudaStream_t s2;
    cudaStreamCreateWithFlags(&s2, cudaStreamNonBlocking);
    cudaEvent_t evFork, evJoin;
    cudaEventCreateWithFlags(&evFork, cudaEventDisableTiming);
    cudaEventCreateWithFlags(&evJoin, cudaEventDisableTiming);

    // zero scratch (async memsets; not kernel launches)
    cudaMemsetAsync(agg_g,  0, (size_t)N_G  * 64 * sizeof(float));
    cudaMemsetAsync(agg_lg, 0, (size_t)N_LG * 64 * sizeof(float));
    cudaMemsetAsync(cnt_g,  0, N_G  * sizeof(float));
    cudaMemsetAsync(cnt_lg, 0, N_LG * sizeof(float));
    cudaMemsetAsync(feat,   0, 128 * sizeof(float));
    cudaEventRecord(evFork, 0);

    // main stream: conv(1), h(2), count(3), DUMMY-MSG(4 -> ncu target), build(5)
    k_conv_w2<<<(32 * 4096) / 256, 256>>>(g_w2);
    k_h<<<(E_G * 32 + 255) / 256, 256>>>(g_ea, g_w1, g_b1, E_G);
    k_count<<<(E_G + 255) / 256, 256>>>(g_ei, E_G, cnt_g);
    // instrumentation: g-branch msg into a sink buffer; identical memory behavior,
    // zero effect on results (dummy sink; no lg blocks launched).
    k_msg_both<<<E_G / 8, 256>>>(x_g, W_g, g_ei, E_G, dummy, E_G / 8,
                                 x_lg, lg_ea, lg_ei, E_LG, dummy);
    dim3 gw(16, 125);
    k_build_W_bf16<<<gw, 256>>>(g_b2, W_g);

    // side stream: second count + inits + lg prep, overlapped with build
    cudaStreamWaitEvent(s2, evFork, 0);
    k_count<<<(E_LG + 255) / 256, 256, 0, s2>>>(lg_ei, E_LG, cnt_lg);
    k_init_x<<<(N_G * 64 + 255) / 256, 256, 0, s2>>>(gx, 20, lin0_w, lin0_b, N_G, x_g);
    k_init_x<<<(N_LG * 64 + 255) / 256, 256, 0, s2>>>(lgx, 5, lin0lg_w, lin0lg_b, N_LG, x_lg);
    k_zero_prep<<<1, 128, 0, s2>>>();
    k_lg_prep<<<1, 64, 0, s2>>>(lg_w1, lg_b1);
    k_lg_tables<<<65, 256, 0, s2>>>(lg_w1, lg_b1, lg_w2, lg_b2);
    k_lg_seg<<<(E_LG + 255) / 256, 256, 0, s2>>>(lg_ea, E_LG);
    k_lg_scan<<<1, 128, 0, s2>>>();
    k_lg_scatter<<<(E_LG + 255) / 256, 256, 0, s2>>>(E_LG);
    cudaEventRecord(evJoin, s2);
    cudaStreamWaitEvent(0, evJoin, 0);

    // 3 NNConv iterations, g+lg fused per phase
    const int nbg_msg = E_G / 8;
    const int lg_tiles_max = ((E_LG / 64 + 66) + 31) & ~31;
    const int nbg_upd = (N_G + 7) / 8;
    const int nblg_upd = (N_LG + 7) / 8;
    for (int it = 0; it < 3; it++) {
        k_msg_both<<<nbg_msg + lg_tiles_max, 256>>>(
            x_g, W_g, g_ei, E_G, agg_g, nbg_msg,
            x_lg, lg_ea, lg_ei, E_LG, agg_lg);
        k_update_both<<<nbg_upd + nblg_upd, 512>>>(
            x_g, g_root, g_bias, cnt_g, agg_g, N_G, nbg_upd,
            x_lg, lg_root, lg_bias, cnt_lg, agg_lg, N_LG);
    }

    // fused sum pooling
    k_pool_both<<<240, 256>>>(x_g, N_G, x_lg, N_LG, feat);

    // head MLP -> scalar
    k_head<<<1, 384>>>(adduct, bott_w, bott_b, lin1_w, lin1_b, lin2_w, lin2_b,
                       (float*)d_out);
}

// round 15
// speedup vs baseline: 1.2625x; 1.0819x over previous
#include <cuda_runtime.h>
#include <cuda_bf16.h>
#include <cuda_fp8.h>
#include <cstddef>
#include <cstdint>

// ---------------- scratch (device globals: allocation-free) ----------------
__device__ unsigned char d_W_g [(size_t)60000 * 4096];  // per-edge [64,64] weights (e4m3, x64 scale)
__device__ uint32_t d_w2p [(size_t)32 * 4096];          // bf16x2-packed g_w2 k-pairs
__device__ uint32_t d_hp  [(size_t)60000 * 32];         // bf16x2-packed h k-pairs per edge
__device__ float d_x_g  [(size_t)30000 * 64];
__device__ float d_x_lg [(size_t)60000 * 64];
__device__ float d_agg_g [(size_t)30000 * 64];
__device__ float d_agg_lg[(size_t)60000 * 64];
__device__ float d_cnt_g [30000];
__device__ float d_cnt_lg[60000];
__device__ float d_feat[128];

// lg piecewise-linear machinery
__device__ float d_T[64];
__device__ int   d_m;
__device__ float d_C[(size_t)65 * 4096];
__device__ float d_D[(size_t)65 * 4096];
__device__ int   d_seg[60000];
__device__ int   d_hist[65];
__device__ int   d_cur[65];
__device__ int   d_order[60000];
__device__ int   d_tile_seg[1100];
__device__ int   d_tile_base[1100];
__device__ int   d_tile_cnt[1100];
__device__ int   d_ntiles;

#define W_SCALE 64.0f
#define W_INV_SCALE 0.015625f

// ---------------- small utility kernels ----------------
__global__ void k_zero_prep() {
    int t = threadIdx.x;
    if (t < 65) d_hist[t] = 0;
    if (t == 65) d_ntiles = 0;
}

// pack w2 into bf16x2 k-pairs
__global__ void k_conv_w2(const float* __restrict__ w2) {
    int i = blockIdx.x * 256 + threadIdx.x;   // 32*4096 items
    int kp = i >> 12, c = i & 4095;
    __nv_bfloat162 p = __floats2bfloat162_rn(w2[(size_t)(2 * kp) * 4096 + c],
                                             w2[(size_t)(2 * kp + 1) * 4096 + c]);
    d_w2p[i] = *(uint32_t*)&p;
}

// h = relu(ea @ w1 + b1), packed bf16x2 pairs, computed once per edge
__global__ void k_h(const float* __restrict__ ea,
                    const float* __restrict__ w1, const float* __restrict__ b1, int E) {
    int idx = blockIdx.x * 256 + threadIdx.x;   // E*32 items
    if (idx >= E * 32) return;
    int e = idx >> 5, op = idx & 31;
    const float* ear = ea + (size_t)e * 4;
    float h0 = b1[2 * op], h1 = b1[2 * op + 1];
#pragma unroll
    for (int f = 0; f < 4; f++) {
        h0 = fmaf(ear[f], w1[f * 64 + 2 * op], h0);
        h1 = fmaf(ear[f], w1[f * 64 + 2 * op + 1], h1);
    }
    __nv_bfloat162 p = __floats2bfloat162_rn(fmaxf(h0, 0.f), fmaxf(h1, 0.f));
    d_hp[idx] = *(uint32_t*)&p;
}

__global__ void k_count(const int* __restrict__ ei, int E, float* __restrict__ cnt) {
    int e = blockIdx.x * 256 + threadIdx.x;
    if (e < E) atomicAdd(&cnt[ei[E + e]], 1.0f);
}

// x0 = relu(xin @ w + b)
__global__ void k_init_x(const float* __restrict__ xin, int F,
                         const float* __restrict__ w, const float* __restrict__ b,
                         int N, float* __restrict__ xout) {
    int idx = blockIdx.x * 256 + threadIdx.x;
    if (idx >= N * 64) return;
    int n = idx >> 6, o = idx & 63;
    const float* xr = xin + (size_t)n * F;
    float acc = b[o];
    for (int f = 0; f < F; f++) acc = fmaf(xr[f], w[f * 64 + o], acc);
    xout[idx] = fmaxf(acc, 0.f);
}

// ---------------- g W build: persistent w2 slab, 15 edge-tiles per block ----------------
__global__ void k_build_W_bf16(const float* __restrict__ b2,
                               unsigned char* __restrict__ W) {
    __shared__ uint32_t sh_wp[32][264];
    __shared__ uint32_t sh_hp[32][36];
    __shared__ unsigned char sh_o[32][256];

    int tid = threadIdx.x;
    int lane = tid & 31, wid = tid >> 5;
    int c0 = blockIdx.x * 256;

#pragma unroll
    for (int k = 0; k < 32; k++) {
        int idx = k * 256 + tid;
        int kp = idx >> 8, cc = idx & 255;
        sh_wp[kp][cc] = d_w2p[(size_t)kp * 4096 + c0 + cc];
    }

    int warp_m = wid & 1;
    int warp_n = wid >> 1;
    int gid = lane >> 2, t4 = lane & 3;
    int r = lane >> 2, q = lane & 3;

    for (int t = 0; t < 15; t++) {
        int e0 = (blockIdx.y * 15 + t) * 32;
        __syncthreads();
#pragma unroll
        for (int k = 0; k < 4; k++) {
            int idx = k * 256 + tid;
            sh_hp[idx >> 5][idx & 31] = d_hp[(size_t)e0 * 32 + idx];
        }
        __syncthreads();

        float c[8][4];
#pragma unroll
        for (int j = 0; j < 8; j++)
#pragma unroll
            for (int qq = 0; qq < 4; qq++) c[j][qq] = 0.f;

#pragma unroll
        for (int kc = 0; kc < 4; kc++) {
            int row = warp_m * 16 + gid;
            uint32_t a0 = sh_hp[row][kc * 8 + t4];
            uint32_t a1 = sh_hp[row + 8][kc * 8 + t4];
            uint32_t a2 = sh_hp[row][kc * 8 + 4 + t4];
            uint32_t a3 = sh_hp[row + 8][kc * 8 + 4 + t4];
#pragma unroll
            for (int j = 0; j < 8; j++) {
                int bn = warp_n * 64 + j * 8 + gid;
                uint32_t b0 = sh_wp[kc * 8 + t4][bn];
                uint32_t b1r = sh_wp[kc * 8 + t4 + 4][bn];
                asm volatile(
                    "mma.sync.aligned.m16n8k16.row.col.f32.bf16.bf16.f32 "
                    "{%0,%1,%2,%3}, {%4,%5,%6,%7}, {%8,%9}, {%0,%1,%2,%3};"
                    : "+f"(c[j][0]), "+f"(c[j][1]), "+f"(c[j][2]), "+f"(c[j][3])
                    : "r"(a0), "r"(a1), "r"(a2), "r"(a3), "r"(b0), "r"(b1r));
            }
        }

#pragma unroll
        for (int j = 0; j < 8; j++) {
            int colL = warp_n * 64 + j * 8 + q * 2;
            float2 bb = *(const float2*)&b2[c0 + colL];
            int rowA = warp_m * 16 + r;
            __nv_fp8x2_storage_t pA = __nv_cvt_float2_to_fp8x2(
                make_float2((c[j][0] + bb.x) * W_SCALE, (c[j][1] + bb.y) * W_SCALE),
                __NV_SATFINITE, __NV_E4M3);
            __nv_fp8x2_storage_t pB = __nv_cvt_float2_to_fp8x2(
                make_float2((c[j][2] + bb.x) * W_SCALE, (c[j][3] + bb.y) * W_SCALE),
                __NV_SATFINITE, __NV_E4M3);
            *(unsigned short*)&sh_o[rowA][colL]     = (unsigned short)pA;
            *(unsigned short*)&sh_o[rowA + 8][colL] = (unsigned short)pB;
        }
        __syncthreads();

        const uint4* src = (const uint4*)&sh_o[0][0];
#pragma unroll
        for (int k = 0; k < 2; k++) {
            int idx = k * 256 + tid;
            int row = idx >> 4, chunk = idx & 15;
            *(uint4*)&W[(size_t)(e0 + row) * 4096 + c0 + chunk * 16] = src[idx];
        }
    }
}

// ---------------- g msg: one warp per edge, fp8 W stream, NO shared memory ----------------
__global__ void k_msg_g(const float* __restrict__ x, const unsigned char* __restrict__ Wg,
                        const int* __restrict__ ei, int E, float* __restrict__ agg) {
    int tid = threadIdx.x;
    int lane = tid & 31;
    int e = (blockIdx.x * 256 + tid) >> 5;
    if (e >= E) return;
    int src = ei[e], tgt = ei[E + e];
    int half = lane >> 4, q = lane & 15;
    const unsigned char* Wr = Wg + (size_t)e * 4096;
    const float* xs = x + (size_t)src * 64;
    float x0 = xs[lane], x1 = xs[lane + 32];
    float a0 = 0.f, a1 = 0.f, a2 = 0.f, a3 = 0.f;
#pragma unroll 8
    for (int jj = 0; jj < 32; jj++) {
        int i = 2 * jj + half;
        float xv = __shfl_sync(0xffffffffu, (jj < 16) ? x0 : x1, 2 * (jj & 15) + half);
        uint32_t w4 = *(const uint32_t*)(Wr + i * 64 + q * 4);
        __half2 lo = __half2(__nv_cvt_fp8x2_to_halfraw2(
            (__nv_fp8x2_storage_t)(w4 & 0xFFFFu), __NV_E4M3));
        __half2 hi = __half2(__nv_cvt_fp8x2_to_halfraw2(
            (__nv_fp8x2_storage_t)(w4 >> 16), __NV_E4M3));
        float2 f0 = __half22float2(lo), f1 = __half22float2(hi);
        a0 = fmaf(xv, f0.x, a0);
        a1 = fmaf(xv, f0.y, a1);
        a2 = fmaf(xv, f1.x, a2);
        a3 = fmaf(xv, f1.y, a3);
    }
    a0 += __shfl_xor_sync(0xffffffffu, a0, 16);
    a1 += __shfl_xor_sync(0xffffffffu, a1, 16);
    a2 += __shfl_xor_sync(0xffffffffu, a2, 16);
    a3 += __shfl_xor_sync(0xffffffffu, a3, 16);
    if (half == 0) {
        float* ag = agg + (size_t)tgt * 64 + q * 4;
        atomicAdd(ag,     a0 * W_INV_SCALE);
        atomicAdd(ag + 1, a1 * W_INV_SCALE);
        atomicAdd(ag + 2, a2 * W_INV_SCALE);
        atomicAdd(ag + 3, a3 * W_INV_SCALE);
    }
}

// ---------------- lg msg: tiles of 64 edges sharing one segment's C/D ----------------
__global__ void k_msg_lg(const float* __restrict__ x, const float* __restrict__ ea,
                         const int* __restrict__ ei, int E, float* __restrict__ agg) {
    int bt = blockIdx.x;
    if (bt >= d_ntiles) return;
    int s = d_tile_seg[bt], base = d_tile_base[bt], cnt = d_tile_cnt[bt];
    __shared__ float sC[4096], sD[4096];
    int tid = threadIdx.x;  // 256
    const float* C = d_C + (size_t)s * 4096;
    const float* Dp = d_D + (size_t)s * 4096;
    for (int i = tid; i < 4096; i += 256) { sC[i] = C[i]; sD[i] = Dp[i]; }
    __syncthreads();
    int wid = tid >> 5, lane = tid & 31;
    const float2* C2 = (const float2*)sC;
    const float2* D2 = (const float2*)sD;
#pragma unroll
    for (int p = 0; p < 4; p++) {
        int slotA = p * 16 + wid * 2;
        int slotB = slotA + 1;
        bool vA = slotA < cnt, vB = slotB < cnt;
        int eA = vA ? d_order[base + slotA] : 0;
        int eB = vB ? d_order[base + slotB] : 0;
        int srcA = ei[eA], tgtA = ei[E + eA];
        int srcB = ei[eB], tgtB = ei[E + eB];
        float eaA = ea[eA], eaB = ea[eB];
        float xA0 = vA ? x[(size_t)srcA * 64 + lane] : 0.f;
        float xA1 = vA ? x[(size_t)srcA * 64 + lane + 32] : 0.f;
        float xB0 = vB ? x[(size_t)srcB * 64 + lane] : 0.f;
        float xB1 = vB ? x[(size_t)srcB * 64 + lane + 32] : 0.f;
        float cA0 = 0, cA1 = 0, dA0 = 0, dA1 = 0;
        float cB0 = 0, cB1 = 0, dB0 = 0, dB1 = 0;
#pragma unroll 8
        for (int i = 0; i < 64; i++) {
            float2 cv = C2[i * 32 + lane];
            float2 dv = D2[i * 32 + lane];
            float xa = __shfl_sync(0xffffffffu, (i < 32) ? xA0 : xA1, i & 31);
            float xb = __shfl_sync(0xffffffffu, (i < 32) ? xB0 : xB1, i & 31);
            cA0 = fmaf(xa, cv.x, cA0); cA1 = fmaf(xa, cv.y, cA1);
            dA0 = fmaf(xa, dv.x, dA0); dA1 = fmaf(xa, dv.y, dA1);
            cB0 = fmaf(xb, cv.x, cB0); cB1 = fmaf(xb, cv.y, cB1);
            dB0 = fmaf(xb, dv.x, dB0); dB1 = fmaf(xb, dv.y, dB1);
        }
        if (vA) {
            float* ag = agg + (size_t)tgtA * 64 + lane * 2;
            atomicAdd(ag,     fmaf(eaA, dA0, cA0));
            atomicAdd(ag + 1, fmaf(eaA, dA1, cA1));
        }
        if (vB) {
            float* ag = agg + (size_t)tgtB * 64 + lane * 2;
            atomicAdd(ag,     fmaf(eaB, dB0, cB0));
            atomicAdd(ag + 1, fmaf(eaB, dB1, cB1));
        }
    }
}

// ---------------- node update (single branch) ----------------
__global__ void k_update(float* __restrict__ x, const float* __restrict__ root,
                         const float* __restrict__ bias, const float* __restrict__ cnt,
                         float* __restrict__ agg, int N) {
    __shared__ float sroot[4096];
    __shared__ float sx[8][64];
    int t = threadIdx.x;  // 512
    for (int k = t; k < 4096; k += 512) sroot[k] = root[k];
    int nl = t >> 6, o = t & 63;
    int n = blockIdx.x * 8 + nl;
    if (n < N) sx[nl][o] = x[(size_t)n * 64 + o];
    __syncthreads();
    if (n >= N) return;
    float acc = bias[o] + agg[(size_t)n * 64 + o] / fmaxf(cnt[n], 1.0f);
#pragma unroll
    for (int i = 0; i < 64; i++) acc = fmaf(sx[nl][i], sroot[i * 64 + o], acc);
    x[(size_t)n * 64 + o] = fmaxf(acc, 0.f);
    agg[(size_t)n * 64 + o] = 0.f;
}

// ---------------- lg piecewise-linear precompute ----------------
__global__ void k_lg_prep(const float* __restrict__ w1, const float* __restrict__ b1) {
    __shared__ float ts[64];
    __shared__ int cnt;
    int j = threadIdx.x;  // 64
    if (j == 0) cnt = 0;
    __syncthreads();
    float w = w1[j], b = b1[j];
    if (w != 0.f) {
        float t = -b / w;
        if (t > 0.f && t < 1.f) {
            int p = atomicAdd(&cnt, 1);
            ts[p] = t;
        }
    }
    __syncthreads();
    if (j == 0) {
        for (int i = 1; i < cnt; i++) {
            float v = ts[i];
            int k = i;
            while (k > 0 && ts[k - 1] > v) { ts[k] = ts[k - 1]; k--; }
            ts[k] = v;
        }
        d_m = cnt;
        for (int i = 0; i < cnt; i++) d_T[i] = ts[i];
    }
}

__global__ void k_lg_tables(const float* __restrict__ w1, const float* __restrict__ b1,
                            const float* __restrict__ w2, const float* __restrict__ b2) {
    int s = blockIdx.x;
    int m = d_m;
    if (s > m) return;
    float lo = (s == 0) ? 0.f : d_T[s - 1];
    float hi = (s == m) ? 1.f : d_T[s];
    float mid = 0.5f * (lo + hi);
    __shared__ float cb[64], cw[64];
    int t = threadIdx.x;  // 256
    if (t < 64) {
        float w = w1[t], b = b1[t];
        bool act = (fmaf(w, mid, b) > 0.f);
        cb[t] = act ? b : 0.f;
        cw[t] = act ? w : 0.f;
    }
    __syncthreads();
    for (int io = t; io < 4096; io += 256) {
        float c = b2[io], d = 0.f;
#pragma unroll 8
        for (int j = 0; j < 64; j++) {
            float wv = w2[(size_t)j * 4096 + io];
            c = fmaf(cb[j], wv, c);
            d = fmaf(cw[j], wv, d);
        }
        d_C[(size_t)s * 4096 + io] = c;
        d_D[(size_t)s * 4096 + io] = d;
    }
}

__global__ void k_lg_seg(const float* __restrict__ ea, int E) {
    int e = blockIdx.x * 256 + threadIdx.x;
    if (e >= E) return;
    float v = ea[e];
    int lo = 0, hi = d_m;
    while (lo < hi) {
        int mid = (lo + hi) >> 1;
        if (d_T[mid] <= v) lo = mid + 1; else hi = mid;
    }
    d_seg[e] = lo;
    atomicAdd(&d_hist[lo], 1);
}

__global__ void k_lg_scan() {
    __shared__ int soff[66], stbase[66], shist[65];
    int ns = d_m + 1;
    int t = threadIdx.x;  // 128
    if (t < ns) shist[t] = d_hist[t];
    __syncthreads();
    if (t == 0) {
        int off = 0, tb = 0;
        for (int s = 0; s < ns; s++) {
            soff[s] = off;
            stbase[s] = tb;
            off += shist[s];
            tb += (shist[s] + 63) >> 6;
        }
        d_ntiles = tb;
    }
    __syncthreads();
    for (int s = t; s < ns; s += blockDim.x) {
        d_cur[s] = soff[s];
        int h = shist[s];
        int nt = (h + 63) >> 6;
        for (int k = 0; k < nt; k++) {
            int idx = stbase[s] + k;
            d_tile_seg[idx] = s;
            d_tile_base[idx] = soff[s] + k * 64;
            d_tile_cnt[idx] = min(64, h - k * 64);
        }
    }
}

__global__ void k_lg_scatter(int E) {
    int e = blockIdx.x * 256 + threadIdx.x;
    if (e >= E) return;
    int s = d_seg[e];
    int p = atomicAdd(&d_cur[s], 1);
    d_order[p] = e;
}

// ---------------- fused sum pooling ----------------
__global__ void k_pool_both(const float* __restrict__ xg, int Ng,
                            const float* __restrict__ xlg, int Nlg,
                            float* __restrict__ out) {
    __shared__ float sh[256];
    int t = threadIdx.x;
    int o = t & 63, g = t >> 6;
    const float* x; int N; float* op;
    int b = blockIdx.x;
    if (b < 120) { x = xg; N = Ng; op = out; }
    else { b -= 120; x = xlg; N = Nlg; op = out + 64; }
    float acc = 0.f;
#pragma unroll 4
    for (int n = b * 4 + g; n < N; n += 120 * 4)
        acc += x[(size_t)n * 64 + o];
    sh[t] = acc;
    __syncthreads();
    if (g == 0)
        atomicAdd(&op[o], sh[o] + sh[64 + o] + sh[128 + o] + sh[192 + o]);
}

// ---------------- head MLP ----------------
__global__ void k_head(const float* __restrict__ adduct,
                       const float* __restrict__ bw, const float* __restrict__ bb,
                       const float* __restrict__ l1w, const float* __restrict__ l1b,
                       const float* __restrict__ l2w, const float* __restrict__ l2b,
                       float* __restrict__ out) {
    __shared__ float a[384];
    __shared__ float red[384];
    int t = threadIdx.x;  // 384
    float acc = bb[t];
#pragma unroll 8
    for (int i = 0; i < 128; i++) acc = fmaf(d_feat[i], bw[i * 384 + t], acc);
    for (int k = 0; k < 3; k++) acc = fmaf(adduct[k], bw[(128 + k) * 384 + t], acc);
    a[t] = fmaxf(acc, 0.f);
    __syncthreads();
    for (int l = 0; l < 6; l++) {
        float s = l1b[t];
#pragma unroll 8
        for (int i = 0; i < 384; i++) s = fmaf(a[i], l1w[i * 384 + t], s);
        __syncthreads();
        a[t] = fmaxf(s, 0.f);
        __syncthreads();
    }
    red[t] = a[t] * l2w[t];
    __syncthreads();
    for (int s = 192; s >= 6; s >>= 1) {
        if (t < s) red[t] += red[t + s];
        __syncthreads();
    }
    if (t == 0)
        out[0] = red[0] + red[1] + red[2] + red[3] + red[4] + red[5] + l2b[0];
}

// ---------------- launch ----------------
extern "C" void kernel_launch(void* const* d_in, const int* in_sizes, int n_in,
                              void* d_out, int out_size) {
    const float* gx       = (const float*)d_in[0];
    const int*   g_ei     = (const int*)  d_in[1];
    const float* g_ea     = (const float*)d_in[2];
    const float* lgx      = (const float*)d_in[3];
    const int*   lg_ei    = (const int*)  d_in[4];
    const float* lg_ea    = (const float*)d_in[5];
    const float* adduct   = (const float*)d_in[6];
    const float* lin0_w   = (const float*)d_in[7];
    const float* lin0_b   = (const float*)d_in[8];
    const float* g_w1     = (const float*)d_in[9];
    const float* g_b1     = (const float*)d_in[10];
    const float* g_w2     = (const float*)d_in[11];
    const float* g_b2     = (const float*)d_in[12];
    const float* g_root   = (const float*)d_in[13];
    const float* g_bias   = (const float*)d_in[14];
    const float* lin0lg_w = (const float*)d_in[15];
    const float* lin0lg_b = (const float*)d_in[16];
    const float* lg_w1    = (const float*)d_in[17];
    const float* lg_b1    = (const float*)d_in[18];
    const float* lg_w2    = (const float*)d_in[19];
    const float* lg_b2    = (const float*)d_in[20];
    const float* lg_root  = (const float*)d_in[21];
    const float* lg_bias  = (const float*)d_in[22];
    const float* bott_w   = (const float*)d_in[23];
    const float* bott_b   = (const float*)d_in[24];
    const float* lin1_w   = (const float*)d_in[25];
    const float* lin1_b   = (const float*)d_in[26];
    const float* lin2_w   = (const float*)d_in[27];
    const float* lin2_b   = (const float*)d_in[28];

    const int N_G = 30000, E_G = 60000, N_LG = 60000, E_LG = 60000;

    unsigned char* W_g;
    float *x_g, *x_lg, *agg_g, *agg_lg, *cnt_g, *cnt_lg, *feat;
    cudaGetSymbolAddress((void**)&W_g,    d_W_g);
    cudaGetSymbolAddress((void**)&x_g,    d_x_g);
    cudaGetSymbolAddress((void**)&x_lg,   d_x_lg);
    cudaGetSymbolAddress((void**)&agg_g,  d_agg_g);
    cudaGetSymbolAddress((void**)&agg_lg, d_agg_lg);
    cudaGetSymbolAddress((void**)&cnt_g,  d_cnt_g);
    cudaGetSymbolAddress((void**)&cnt_lg, d_cnt_lg);
    cudaGetSymbolAddress((void**)&feat,   d_feat);

    // side stream + fork/join events
    cudaStream_t s2;
    cudaStreamCreateWithFlags(&s2, cudaStreamNonBlocking);
    cudaEvent_t evFork, evJoin;
    cudaEventCreateWithFlags(&evFork, cudaEventDisableTiming);
    cudaEventCreateWithFlags(&evJoin, cudaEventDisableTiming);

    // zero scratch (async memsets; not kernel launches)
    cudaMemsetAsync(agg_g,  0, (size_t)N_G  * 64 * sizeof(float));
    cudaMemsetAsync(agg_lg, 0, (size_t)N_LG * 64 * sizeof(float));
    cudaMemsetAsync(cnt_g,  0, N_G  * sizeof(float));
    cudaMemsetAsync(cnt_lg, 0, N_LG * sizeof(float));
    cudaMemsetAsync(feat,   0, 128 * sizeof(float));
    cudaEventRecord(evFork, 0);

    // ===== main stream: ENTIRE g chain =====
    // conv(1), h(2), init_x_g(3), BUILD(4 -> ncu target), count_g(5), loop...
    k_conv_w2<<<(32 * 4096) / 256, 256>>>(g_w2);
    k_h<<<(E_G * 32 + 255) / 256, 256>>>(g_ea, g_w1, g_b1, E_G);
    k_init_x<<<(N_G * 64 + 255) / 256, 256>>>(gx, 20, lin0_w, lin0_b, N_G, x_g);
    dim3 gw(16, 125);
    k_build_W_bf16<<<gw, 256>>>(g_b2, W_g);
    k_count<<<(E_G + 255) / 256, 256>>>(g_ei, E_G, cnt_g);
    for (int it = 0; it < 3; it++) {
        k_msg_g<<<E_G / 8, 256>>>(x_g, W_g, g_ei, E_G, agg_g);
        k_update<<<(N_G + 7) / 8, 512>>>(x_g, g_root, g_bias, cnt_g, agg_g, N_G);
    }

    // ===== side stream: ENTIRE lg chain =====
    cudaStreamWaitEvent(s2, evFork, 0);
    k_count<<<(E_LG + 255) / 256, 256, 0, s2>>>(lg_ei, E_LG, cnt_lg);
    k_init_x<<<(N_LG * 64 + 255) / 256, 256, 0, s2>>>(lgx, 5, lin0lg_w, lin0lg_b, N_LG, x_lg);
    k_zero_prep<<<1, 128, 0, s2>>>();
    k_lg_prep<<<1, 64, 0, s2>>>(lg_w1, lg_b1);
    k_lg_tables<<<65, 256, 0, s2>>>(lg_w1, lg_b1, lg_w2, lg_b2);
    k_lg_seg<<<(E_LG + 255) / 256, 256, 0, s2>>>(lg_ea, E_LG);
    k_lg_scan<<<1, 128, 0, s2>>>();
    k_lg_scatter<<<(E_LG + 255) / 256, 256, 0, s2>>>(E_LG);
    const int lg_tiles_max = ((E_LG / 64 + 66) + 31) & ~31;
    for (int it = 0; it < 3; it++) {
        k_msg_lg<<<lg_tiles_max, 256, 0, s2>>>(x_lg, lg_ea, lg_ei, E_LG, agg_lg);
        k_update<<<(N_LG + 7) / 8, 512, 0, s2>>>(x_lg, lg_root, lg_bias, cnt_lg, agg_lg, N_LG);
    }
    cudaEventRecord(evJoin, s2);
    cudaStreamWaitEvent(0, evJoin, 0);

    // ===== join: pooling + head =====
    k_pool_both<<<240, 256>>>(x_g, N_G, x_lg, N_LG, feat);
    k_head<<<1, 384>>>(adduct, bott_w, bott_b, lin1_w, lin1_b, lin2_w, lin2_b,
                       (float*)d_out);
}

// round 16
// speedup vs baseline: 1.3538x; 1.0723x over previous
#include <cuda_runtime.h>
#include <cuda_bf16.h>
#include <cuda_fp8.h>
#include <cstddef>
#include <cstdint>

// ---------------- scratch (device globals: allocation-free) ----------------
__device__ unsigned char d_W_g [(size_t)60000 * 4096];  // per-edge [64,64] weights (e4m3, x64 scale)
__device__ uint32_t d_w2p [(size_t)32 * 4096];          // bf16x2-packed g_w2 k-pairs
__device__ uint32_t d_hp  [(size_t)60000 * 32];         // bf16x2-packed h k-pairs per edge
__device__ float d_x_g  [(size_t)30000 * 64];
__device__ float d_x_lg [(size_t)60000 * 64];
__device__ float d_agg_g [(size_t)30000 * 64];
__device__ float d_agg_lg[(size_t)60000 * 64];
__device__ float d_cnt_g [30000];
__device__ float d_cnt_lg[60000];
__device__ float d_feat[128];

// lg piecewise-linear machinery
__device__ float d_T[64];
__device__ int   d_m;
__device__ float d_C[(size_t)65 * 4096];
__device__ float d_D[(size_t)65 * 4096];
__device__ int   d_seg[60000];
__device__ int   d_hist[65];
__device__ int   d_cur[65];
__device__ int   d_order[60000];
__device__ int   d_tile_seg[1100];
__device__ int   d_tile_base[1100];
__device__ int   d_tile_cnt[1100];
__device__ int   d_ntiles;

#define W_SCALE 64.0f
#define W_INV_SCALE 0.015625f

// ---------------- small utility kernels ----------------
__global__ void k_zero_prep() {
    int t = threadIdx.x;
    if (t < 65) d_hist[t] = 0;
    if (t == 65) d_ntiles = 0;
}

// pack w2 into bf16x2 k-pairs
__global__ void k_conv_w2(const float* __restrict__ w2) {
    int i = blockIdx.x * 256 + threadIdx.x;   // 32*4096 items
    int kp = i >> 12, c = i & 4095;
    __nv_bfloat162 p = __floats2bfloat162_rn(w2[(size_t)(2 * kp) * 4096 + c],
                                             w2[(size_t)(2 * kp + 1) * 4096 + c]);
    d_w2p[i] = *(uint32_t*)&p;
}

// h = relu(ea @ w1 + b1), packed bf16x2 pairs, once per edge
__global__ void k_h(const float* __restrict__ ea,
                    const float* __restrict__ w1, const float* __restrict__ b1, int E) {
    int idx = blockIdx.x * 256 + threadIdx.x;   // E*32 items
    if (idx >= E * 32) return;
    int e = idx >> 5, op = idx & 31;
    const float* ear = ea + (size_t)e * 4;
    float h0 = b1[2 * op], h1 = b1[2 * op + 1];
#pragma unroll
    for (int f = 0; f < 4; f++) {
        h0 = fmaf(ear[f], w1[f * 64 + 2 * op], h0);
        h1 = fmaf(ear[f], w1[f * 64 + 2 * op + 1], h1);
    }
    __nv_bfloat162 p = __floats2bfloat162_rn(fmaxf(h0, 0.f), fmaxf(h1, 0.f));
    d_hp[idx] = *(uint32_t*)&p;
}

__global__ void k_count(const int* __restrict__ ei, int E, float* __restrict__ cnt) {
    int e = blockIdx.x * 256 + threadIdx.x;
    if (e < E) atomicAdd(&cnt[ei[E + e]], 1.0f);
}

// x0 = relu(xin @ w + b)
__global__ void k_init_x(const float* __restrict__ xin, int F,
                         const float* __restrict__ w, const float* __restrict__ b,
                         int N, float* __restrict__ xout) {
    int idx = blockIdx.x * 256 + threadIdx.x;
    if (idx >= N * 64) return;
    int n = idx >> 6, o = idx & 63;
    const float* xr = xin + (size_t)n * F;
    float acc = b[o];
    for (int f = 0; f < F; f++) acc = fmaf(xr[f], w[f * 64 + o], acc);
    xout[idx] = fmaxf(acc, 0.f);
}

// ---------------- g W build: persistent w2 slab + REGISTER-RESIDENT b-fragments ----------------
// grid (16 col-blocks, 125 edge-groups); b-frags hoisted out of the 15-tile loop.
__global__ void __launch_bounds__(256, 2)
k_build_W_bf16(const float* __restrict__ b2, unsigned char* __restrict__ W) {
    __shared__ uint32_t sh_wp[32][264];
    __shared__ uint32_t sh_hp[32][36];
    __shared__ unsigned char sh_o[32][256];

    int tid = threadIdx.x;
    int lane = tid & 31, wid = tid >> 5;
    int c0 = blockIdx.x * 256;

    // stage full w2 slab once
#pragma unroll
    for (int k = 0; k < 32; k++) {
        int idx = k * 256 + tid;
        int kp = idx >> 8, cc = idx & 255;
        sh_wp[kp][cc] = d_w2p[(size_t)kp * 4096 + c0 + cc];
    }
    __syncthreads();

    int warp_m = wid & 1;
    int warp_n = wid >> 1;
    int gid = lane >> 2, t4 = lane & 3;
    int r = lane >> 2, q = lane & 3;

    // hoist b-fragments into registers (tile-invariant)
    uint32_t breg[4][8][2];
#pragma unroll
    for (int kc = 0; kc < 4; kc++)
#pragma unroll
        for (int j = 0; j < 8; j++) {
            int bn = warp_n * 64 + j * 8 + gid;
            breg[kc][j][0] = sh_wp[kc * 8 + t4][bn];
            breg[kc][j][1] = sh_wp[kc * 8 + t4 + 4][bn];
        }

    for (int t = 0; t < 15; t++) {
        int e0 = (blockIdx.y * 15 + t) * 32;
        __syncthreads();   // prev tile's sh_hp reads + sh_o copy-out complete
#pragma unroll
        for (int k = 0; k < 4; k++) {
            int idx = k * 256 + tid;
            sh_hp[idx >> 5][idx & 31] = d_hp[(size_t)e0 * 32 + idx];
        }
        __syncthreads();

        float c[8][4];
#pragma unroll
        for (int j = 0; j < 8; j++)
#pragma unroll
            for (int qq = 0; qq < 4; qq++) c[j][qq] = 0.f;

#pragma unroll
        for (int kc = 0; kc < 4; kc++) {
            int row = warp_m * 16 + gid;
            uint32_t a0 = sh_hp[row][kc * 8 + t4];
            uint32_t a1 = sh_hp[row + 8][kc * 8 + t4];
            uint32_t a2 = sh_hp[row][kc * 8 + 4 + t4];
            uint32_t a3 = sh_hp[row + 8][kc * 8 + 4 + t4];
#pragma unroll
            for (int j = 0; j < 8; j++) {
                asm volatile(
                    "mma.sync.aligned.m16n8k16.row.col.f32.bf16.bf16.f32 "
                    "{%0,%1,%2,%3}, {%4,%5,%6,%7}, {%8,%9}, {%0,%1,%2,%3};"
                    : "+f"(c[j][0]), "+f"(c[j][1]), "+f"(c[j][2]), "+f"(c[j][3])
                    : "r"(a0), "r"(a1), "r"(a2), "r"(a3),
                      "r"(breg[kc][j][0]), "r"(breg[kc][j][1]));
            }
        }

#pragma unroll
        for (int j = 0; j < 8; j++) {
            int colL = warp_n * 64 + j * 8 + q * 2;
            float2 bb = *(const float2*)&b2[c0 + colL];
            int rowA = warp_m * 16 + r;
            __nv_fp8x2_storage_t pA = __nv_cvt_float2_to_fp8x2(
                make_float2((c[j][0] + bb.x) * W_SCALE, (c[j][1] + bb.y) * W_SCALE),
                __NV_SATFINITE, __NV_E4M3);
            __nv_fp8x2_storage_t pB = __nv_cvt_float2_to_fp8x2(
                make_float2((c[j][2] + bb.x) * W_SCALE, (c[j][3] + bb.y) * W_SCALE),
                __NV_SATFINITE, __NV_E4M3);
            *(unsigned short*)&sh_o[rowA][colL]     = (unsigned short)pA;
            *(unsigned short*)&sh_o[rowA + 8][colL] = (unsigned short)pB;
        }
        __syncthreads();

        const uint4* src = (const uint4*)&sh_o[0][0];
#pragma unroll
        for (int k = 0; k < 2; k++) {
            int idx = k * 256 + tid;
            int row = idx >> 4, chunk = idx & 15;
            *(uint4*)&W[(size_t)(e0 + row) * 4096 + c0 + chunk * 16] = src[idx];
        }
    }
}

// ---------------- g msg: one warp per edge, fp8 W stream, no smem ----------------
__global__ void k_msg_g(const float* __restrict__ x, const unsigned char* __restrict__ Wg,
                        const int* __restrict__ ei, int E, float* __restrict__ agg) {
    int tid = threadIdx.x;
    int lane = tid & 31;
    int e = (blockIdx.x * 256 + tid) >> 5;
    if (e >= E) return;
    int src = ei[e], tgt = ei[E + e];
    int half = lane >> 4, q = lane & 15;
    const unsigned char* Wr = Wg + (size_t)e * 4096;
    const float* xs = x + (size_t)src * 64;
    float x0 = xs[lane], x1 = xs[lane + 32];
    float a0 = 0.f, a1 = 0.f, a2 = 0.f, a3 = 0.f;
#pragma unroll 8
    for (int jj = 0; jj < 32; jj++) {
        int i = 2 * jj + half;
        float xv = __shfl_sync(0xffffffffu, (jj < 16) ? x0 : x1, 2 * (jj & 15) + half);
        uint32_t w4 = *(const uint32_t*)(Wr + i * 64 + q * 4);
        __half2 lo = __half2(__nv_cvt_fp8x2_to_halfraw2(
            (__nv_fp8x2_storage_t)(w4 & 0xFFFFu), __NV_E4M3));
        __half2 hi = __half2(__nv_cvt_fp8x2_to_halfraw2(
            (__nv_fp8x2_storage_t)(w4 >> 16), __NV_E4M3));
        float2 f0 = __half22float2(lo), f1 = __half22float2(hi);
        a0 = fmaf(xv, f0.x, a0);
        a1 = fmaf(xv, f0.y, a1);
        a2 = fmaf(xv, f1.x, a2);
        a3 = fmaf(xv, f1.y, a3);
    }
    a0 += __shfl_xor_sync(0xffffffffu, a0, 16);
    a1 += __shfl_xor_sync(0xffffffffu, a1, 16);
    a2 += __shfl_xor_sync(0xffffffffu, a2, 16);
    a3 += __shfl_xor_sync(0xffffffffu, a3, 16);
    if (half == 0) {
        float* ag = agg + (size_t)tgt * 64 + q * 4;
        atomicAdd(ag,     a0 * W_INV_SCALE);
        atomicAdd(ag + 1, a1 * W_INV_SCALE);
        atomicAdd(ag + 2, a2 * W_INV_SCALE);
        atomicAdd(ag + 3, a3 * W_INV_SCALE);
    }
}

// ---------------- lg msg: tiles of 64 edges sharing one segment's C/D ----------------
__global__ void k_msg_lg(const float* __restrict__ x, const float* __restrict__ ea,
                         const int* __restrict__ ei, int E, float* __restrict__ agg) {
    int bt = blockIdx.x;
    if (bt >= d_ntiles) return;
    int s = d_tile_seg[bt], base = d_tile_base[bt], cnt = d_tile_cnt[bt];
    __shared__ float sC[4096], sD[4096];
    int tid = threadIdx.x;  // 256
    const float* C = d_C + (size_t)s * 4096;
    const float* Dp = d_D + (size_t)s * 4096;
    for (int i = tid; i < 4096; i += 256) { sC[i] = C[i]; sD[i] = Dp[i]; }
    __syncthreads();
    int wid = tid >> 5, lane = tid & 31;
    const float2* C2 = (const float2*)sC;
    const float2* D2 = (const float2*)sD;
#pragma unroll
    for (int p = 0; p < 4; p++) {
        int slotA = p * 16 + wid * 2;
        int slotB = slotA + 1;
        bool vA = slotA < cnt, vB = slotB < cnt;
        int eA = vA ? d_order[base + slotA] : 0;
        int eB = vB ? d_order[base + slotB] : 0;
        int srcA = ei[eA], tgtA = ei[E + eA];
        int srcB = ei[eB], tgtB = ei[E + eB];
        float eaA = ea[eA], eaB = ea[eB];
        float xA0 = vA ? x[(size_t)srcA * 64 + lane] : 0.f;
        float xA1 = vA ? x[(size_t)srcA * 64 + lane + 32] : 0.f;
        float xB0 = vB ? x[(size_t)srcB * 64 + lane] : 0.f;
        float xB1 = vB ? x[(size_t)srcB * 64 + lane + 32] : 0.f;
        float cA0 = 0, cA1 = 0, dA0 = 0, dA1 = 0;
        float cB0 = 0, cB1 = 0, dB0 = 0, dB1 = 0;
#pragma unroll 8
        for (int i = 0; i < 64; i++) {
            float2 cv = C2[i * 32 + lane];
            float2 dv = D2[i * 32 + lane];
            float xa = __shfl_sync(0xffffffffu, (i < 32) ? xA0 : xA1, i & 31);
            float xb = __shfl_sync(0xffffffffu, (i < 32) ? xB0 : xB1, i & 31);
            cA0 = fmaf(xa, cv.x, cA0); cA1 = fmaf(xa, cv.y, cA1);
            dA0 = fmaf(xa, dv.x, dA0); dA1 = fmaf(xa, dv.y, dA1);
            cB0 = fmaf(xb, cv.x, cB0); cB1 = fmaf(xb, cv.y, cB1);
            dB0 = fmaf(xb, dv.x, dB0); dB1 = fmaf(xb, dv.y, dB1);
        }
        if (vA) {
            float* ag = agg + (size_t)tgtA * 64 + lane * 2;
            atomicAdd(ag,     fmaf(eaA, dA0, cA0));
            atomicAdd(ag + 1, fmaf(eaA, dA1, cA1));
        }
        if (vB) {
            float* ag = agg + (size_t)tgtB * 64 + lane * 2;
            atomicAdd(ag,     fmaf(eaB, dB0, cB0));
            atomicAdd(ag + 1, fmaf(eaB, dB1, cB1));
        }
    }
}

// ---------------- persistent node update: root staged ONCE per block ----------------
__global__ void k_update_p(float* __restrict__ x, const float* __restrict__ root,
                           const float* __restrict__ bias, const float* __restrict__ cnt,
                           float* __restrict__ agg, int N) {
    __shared__ float sroot[4096];
    __shared__ float sx[8][64];
    int t = threadIdx.x;  // 512
    for (int k = t; k < 4096; k += 512) sroot[k] = root[k];
    int nl = t >> 6, o = t & 63;
    int nvb = (N + 7) / 8;
    for (int b = blockIdx.x; b < nvb; b += gridDim.x) {
        int n = b * 8 + nl;
        __syncthreads();                  // prev iter's sx reads done (and sroot staged)
        if (n < N) sx[nl][o] = x[(size_t)n * 64 + o];
        __syncthreads();
        if (n < N) {
            float acc = bias[o] + agg[(size_t)n * 64 + o] / fmaxf(cnt[n], 1.0f);
#pragma unroll
            for (int i = 0; i < 64; i++) acc = fmaf(sx[nl][i], sroot[i * 64 + o], acc);
            x[(size_t)n * 64 + o] = fmaxf(acc, 0.f);
            agg[(size_t)n * 64 + o] = 0.f;
        }
    }
}

// ---------------- lg piecewise-linear precompute ----------------
__global__ void k_lg_prep(const float* __restrict__ w1, const float* __restrict__ b1) {
    __shared__ float ts[64];
    __shared__ int cnt;
    int j = threadIdx.x;  // 64
    if (j == 0) cnt = 0;
    __syncthreads();
    float w = w1[j], b = b1[j];
    if (w != 0.f) {
        float t = -b / w;
        if (t > 0.f && t < 1.f) {
            int p = atomicAdd(&cnt, 1);
            ts[p] = t;
        }
    }
    __syncthreads();
    if (j == 0) {
        for (int i = 1; i < cnt; i++) {
            float v = ts[i];
            int k = i;
            while (k > 0 && ts[k - 1] > v) { ts[k] = ts[k - 1]; k--; }
            ts[k] = v;
        }
        d_m = cnt;
        for (int i = 0; i < cnt; i++) d_T[i] = ts[i];
    }
}

__global__ void k_lg_tables(const float* __restrict__ w1, const float* __restrict__ b1,
                            const float* __restrict__ w2, const float* __restrict__ b2) {
    int s = blockIdx.x;
    int m = d_m;
    if (s > m) return;
    float lo = (s == 0) ? 0.f : d_T[s - 1];
    float hi = (s == m) ? 1.f : d_T[s];
    float mid = 0.5f * (lo + hi);
    __shared__ float cb[64], cw[64];
    int t = threadIdx.x;  // 256
    if (t < 64) {
        float w = w1[t], b = b1[t];
        bool act = (fmaf(w, mid, b) > 0.f);
        cb[t] = act ? b : 0.f;
        cw[t] = act ? w : 0.f;
    }
    __syncthreads();
    for (int io = t; io < 4096; io += 256) {
        float c = b2[io], d = 0.f;
#pragma unroll 8
        for (int j = 0; j < 64; j++) {
            float wv = w2[(size_t)j * 4096 + io];
            c = fmaf(cb[j], wv, c);
            d = fmaf(cw[j], wv, d);
        }
        d_C[(size_t)s * 4096 + io] = c;
        d_D[(size_t)s * 4096 + io] = d;
    }
}

__global__ void k_lg_seg(const float* __restrict__ ea, int E) {
    int e = blockIdx.x * 256 + threadIdx.x;
    if (e >= E) return;
    float v = ea[e];
    int lo = 0, hi = d_m;
    while (lo < hi) {
        int mid = (lo + hi) >> 1;
        if (d_T[mid] <= v) lo = mid + 1; else hi = mid;
    }
    d_seg[e] = lo;
    atomicAdd(&d_hist[lo], 1);
}

__global__ void k_lg_scan() {
    __shared__ int soff[66], stbase[66], shist[65];
    int ns = d_m + 1;
    int t = threadIdx.x;  // 128
    if (t < ns) shist[t] = d_hist[t];
    __syncthreads();
    if (t == 0) {
        int off = 0, tb = 0;
        for (int s = 0; s < ns; s++) {
            soff[s] = off;
            stbase[s] = tb;
            off += shist[s];
            tb += (shist[s] + 63) >> 6;
        }
        d_ntiles = tb;
    }
    __syncthreads();
    for (int s = t; s < ns; s += blockDim.x) {
        d_cur[s] = soff[s];
        int h = shist[s];
        int nt = (h + 63) >> 6;
        for (int k = 0; k < nt; k++) {
            int idx = stbase[s] + k;
            d_tile_seg[idx] = s;
            d_tile_base[idx] = soff[s] + k * 64;
            d_tile_cnt[idx] = min(64, h - k * 64);
        }
    }
}

__global__ void k_lg_scatter(int E) {
    int e = blockIdx.x * 256 + threadIdx.x;
    if (e >= E) return;
    int s = d_seg[e];
    int p = atomicAdd(&d_cur[s], 1);
    d_order[p] = e;
}

// ---------------- fused sum pooling ----------------
__global__ void k_pool_both(const float* __restrict__ xg, int Ng,
                            const float* __restrict__ xlg, int Nlg,
                            float* __restrict__ out) {
    __shared__ float sh[256];
    int t = threadIdx.x;
    int o = t & 63, g = t >> 6;
    const float* x; int N; float* op;
    int b = blockIdx.x;
    if (b < 120) { x = xg; N = Ng; op = out; }
    else { b -= 120; x = xlg; N = Nlg; op = out + 64; }
    float acc = 0.f;
#pragma unroll 4
    for (int n = b * 4 + g; n < N; n += 120 * 4)
        acc += x[(size_t)n * 64 + o];
    sh[t] = acc;
    __syncthreads();
    if (g == 0)
        atomicAdd(&op[o], sh[o] + sh[64 + o] + sh[128 + o] + sh[192 + o]);
}

// ---------------- head MLP ----------------
__global__ void k_head(const float* __restrict__ adduct,
                       const float* __restrict__ bw, const float* __restrict__ bb,
                       const float* __restrict__ l1w, const float* __restrict__ l1b,
                       const float* __restrict__ l2w, const float* __restrict__ l2b,
                       float* __restrict__ out) {
    __shared__ float a[384];
    __shared__ float red[384];
    int t = threadIdx.x;  // 384
    float acc = bb[t];
#pragma unroll 8
    for (int i = 0; i < 128; i++) acc = fmaf(d_feat[i], bw[i * 384 + t], acc);
    for (int k = 0; k < 3; k++) acc = fmaf(adduct[k], bw[(128 + k) * 384 + t], acc);
    a[t] = fmaxf(acc, 0.f);
    __syncthreads();
    for (int l = 0; l < 6; l++) {
        float s = l1b[t];
#pragma unroll 8
        for (int i = 0; i < 384; i++) s = fmaf(a[i], l1w[i * 384 + t], s);
        __syncthreads();
        a[t] = fmaxf(s, 0.f);
        __syncthreads();
    }
    red[t] = a[t] * l2w[t];
    __syncthreads();
    for (int s = 192; s >= 6; s >>= 1) {
        if (t < s) red[t] += red[t + s];
        __syncthreads();
    }
    if (t == 0)
        out[0] = red[0] + red[1] + red[2] + red[3] + red[4] + red[5] + l2b[0];
}

// ---------------- launch ----------------
extern "C" void kernel_launch(void* const* d_in, const int* in_sizes, int n_in,
                              void* d_out, int out_size) {
    const float* gx       = (const float*)d_in[0];
    const int*   g_ei     = (const int*)  d_in[1];
    const float* g_ea     = (const float*)d_in[2];
    const float* lgx      = (const float*)d_in[3];
    const int*   lg_ei    = (const int*)  d_in[4];
    const float* lg_ea    = (const float*)d_in[5];
    const float* adduct   = (const float*)d_in[6];
    const float* lin0_w   = (const float*)d_in[7];
    const float* lin0_b   = (const float*)d_in[8];
    const float* g_w1     = (const float*)d_in[9];
    const float* g_b1     = (const float*)d_in[10];
    const float* g_w2     = (const float*)d_in[11];
    const float* g_b2     = (const float*)d_in[12];
    const float* g_root   = (const float*)d_in[13];
    const float* g_bias   = (const float*)d_in[14];
    const float* lin0lg_w = (const float*)d_in[15];
    const float* lin0lg_b = (const float*)d_in[16];
    const float* lg_w1    = (const float*)d_in[17];
    const float* lg_b1    = (const float*)d_in[18];
    const float* lg_w2    = (const float*)d_in[19];
    const float* lg_b2    = (const float*)d_in[20];
    const float* lg_root  = (const float*)d_in[21];
    const float* lg_bias  = (const float*)d_in[22];
    const float* bott_w   = (const float*)d_in[23];
    const float* bott_b   = (const float*)d_in[24];
    const float* lin1_w   = (const float*)d_in[25];
    const float* lin1_b   = (const float*)d_in[26];
    const float* lin2_w   = (const float*)d_in[27];
    const float* lin2_b   = (const float*)d_in[28];

    const int N_G = 30000, E_G = 60000, N_LG = 60000, E_LG = 60000;

    unsigned char* W_g;
    float *x_g, *x_lg, *agg_g, *agg_lg, *cnt_g, *cnt_lg, *feat;
    cudaGetSymbolAddress((void**)&W_g,    d_W_g);
    cudaGetSymbolAddress((void**)&x_g,    d_x_g);
    cudaGetSymbolAddress((void**)&x_lg,   d_x_lg);
    cudaGetSymbolAddress((void**)&agg_g,  d_agg_g);
    cudaGetSymbolAddress((void**)&agg_lg, d_agg_lg);
    cudaGetSymbolAddress((void**)&cnt_g,  d_cnt_g);
    cudaGetSymbolAddress((void**)&cnt_lg, d_cnt_lg);
    cudaGetSymbolAddress((void**)&feat,   d_feat);

    // side stream + fork/join events
    cudaStream_t s2;
    cudaStreamCreateWithFlags(&s2, cudaStreamNonBlocking);
    cudaEvent_t evFork, evJoin;
    cudaEventCreateWithFlags(&evFork, cudaEventDisableTiming);
    cudaEventCreateWithFlags(&evJoin, cudaEventDisableTiming);

    // zero scratch (async memsets; not kernel launches)
    cudaMemsetAsync(agg_g,  0, (size_t)N_G  * 64 * sizeof(float));
    cudaMemsetAsync(agg_lg, 0, (size_t)N_LG * 64 * sizeof(float));
    cudaMemsetAsync(cnt_g,  0, N_G  * sizeof(float));
    cudaMemsetAsync(cnt_lg, 0, N_LG * sizeof(float));
    cudaMemsetAsync(feat,   0, 128 * sizeof(float));
    cudaEventRecord(evFork, 0);

    // ===== main stream: ENTIRE g chain =====
    // conv(1), h(2), init_x_g(3), BUILD(4 -> ncu target), count_g(5), loop...
    k_conv_w2<<<(32 * 4096) / 256, 256>>>(g_w2);
    k_h<<<(E_G * 32 + 255) / 256, 256>>>(g_ea, g_w1, g_b1, E_G);
    k_init_x<<<(N_G * 64 + 255) / 256, 256>>>(gx, 20, lin0_w, lin0_b, N_G, x_g);
    dim3 gw(16, 125);
    k_build_W_bf16<<<gw, 256>>>(g_b2, W_g);
    k_count<<<(E_G + 255) / 256, 256>>>(g_ei, E_G, cnt_g);
    for (int it = 0; it < 3; it++) {
        k_msg_g<<<E_G / 8, 256>>>(x_g, W_g, g_ei, E_G, agg_g);
        k_update_p<<<296, 512>>>(x_g, g_root, g_bias, cnt_g, agg_g, N_G);
    }

    // ===== side stream: ENTIRE lg chain =====
    cudaStreamWaitEvent(s2, evFork, 0);
    k_count<<<(E_LG + 255) / 256, 256, 0, s2>>>(lg_ei, E_LG, cnt_lg);
    k_init_x<<<(N_LG * 64 + 255) / 256, 256, 0, s2>>>(lgx, 5, lin0lg_w, lin0lg_b, N_LG, x_lg);
    k_zero_prep<<<1, 128, 0, s2>>>();
    k_lg_prep<<<1, 64, 0, s2>>>(lg_w1, lg_b1);
    k_lg_tables<<<65, 256, 0, s2>>>(lg_w1, lg_b1, lg_w2, lg_b2);
    k_lg_seg<<<(E_LG + 255) / 256, 256, 0, s2>>>(lg_ea, E_LG);
    k_lg_scan<<<1, 128, 0, s2>>>();
    k_lg_scatter<<<(E_LG + 255) / 256, 256, 0, s2>>>(E_LG);
    const int lg_tiles_max = ((E_LG / 64 + 66) + 31) & ~31;
    for (int it = 0; it < 3; it++) {
        k_msg_lg<<<lg_tiles_max, 256, 0, s2>>>(x_lg, lg_ea, lg_ei, E_LG, agg_lg);
        k_update_p<<<296, 512, 0, s2>>>(x_lg, lg_root, lg_bias, cnt_lg, agg_lg, N_LG);
    }
    cudaEventRecord(evJoin, s2);
    cudaStreamWaitEvent(0, evJoin, 0);

    // ===== join: pooling + head =====
    k_pool_both<<<240, 256>>>(x_g, N_G, x_lg, N_LG, feat);
    k_head<<<1, 384>>>(adduct, bott_w, bott_b, lin1_w, lin1_b, lin2_w, lin2_b,
                       (float*)d_out);
}